// round 12
// baseline (speedup 1.0000x reference)
#include <cuda_runtime.h>
#include <cuda_fp16.h>
#include <math.h>
#include <stdint.h>

#define B_  32
#define T_  512
#define C_  512
#define TD_ 256
#define G_  3
#define MROWS 16384
#define KF  3072               // feature K (single stream)

#define MT 128
#define NT 128
#define BK 64
#define NTHR 256
// fp16 gemm smem: per stage A 16K | B 16K = 32K, 3 stages -> 96KB (2 CTA/SM)
#define SOFF_B 16384u
#define SBUF 32768u
#define SMEMS_SZ (3 * 32768)
#define STG_S 133

// ---------------- scratch arena ----------------
#define MB (1024ull * 1024ull)
#define OFF_F     0ull             // features fp16 (16384 x 3072) 96MB (both stages)
#define OFF_Z     (96ull  * MB)    // z fp16: tok 8MB / ch 32MB
#define OFF_CT    (160ull * MB)    // tok coef (256 x 3072) 1.5MB
#define OFF_WT    (162ull * MB)    // tok lw fp16 (512 x 256) 0.25MB
#define OFF_CC    (164ull * MB)    // ch coef (1024 x 3072) 6MB
#define OFF_WC    (172ull * MB)    // ch lw fp16 (512 x 1024) 1MB
#define OFF_ST    (174ull * MB)    // LN1 stats float2 per row (128KB)
#define OFF_X1    (206ull * MB)    // x1 fp32 32MB
__device__ __align__(256) char g_scratch[240ull * MB];

// ---------------- PTX helpers ----------------
__device__ __forceinline__ uint32_t smem_u32(const void* p) {
    uint32_t a;
    asm("{ .reg .u64 t; cvta.to.shared.u64 t, %1; cvt.u32.u64 %0, t; }" : "=r"(a) : "l"(p));
    return a;
}
__device__ __forceinline__ void cpasync16(uint32_t dst, const void* src) {
    asm volatile("cp.async.cg.shared.global [%0], [%1], 16;" :: "r"(dst), "l"(src));
}
__device__ __forceinline__ void cp_commit() { asm volatile("cp.async.commit_group;" ::: "memory"); }
__device__ __forceinline__ void cp_wait0()  { asm volatile("cp.async.wait_group 0;" ::: "memory"); }
__device__ __forceinline__ void cp_wait1()  { asm volatile("cp.async.wait_group 1;" ::: "memory"); }
__device__ __forceinline__ void ldsm4(uint32_t addr, uint32_t r[4]) {
    asm volatile("ldmatrix.sync.aligned.m8n8.x4.shared.b16 {%0,%1,%2,%3}, [%4];"
                 : "=r"(r[0]), "=r"(r[1]), "=r"(r[2]), "=r"(r[3]) : "r"(addr));
}
__device__ __forceinline__ void mma_f16(float d[4], const uint32_t a[4], const uint32_t b[2]) {
    asm volatile(
        "mma.sync.aligned.m16n8k16.row.col.f32.f16.f16.f32 "
        "{%0,%1,%2,%3}, {%4,%5,%6,%7}, {%8,%9}, {%0,%1,%2,%3};"
        : "+f"(d[0]), "+f"(d[1]), "+f"(d[2]), "+f"(d[3])
        : "r"(a[0]), "r"(a[1]), "r"(a[2]), "r"(a[3]), "r"(b[0]), "r"(b[1]));
}
// Polynomial sincos, pure FMA pipe, err < 5e-7 for |v| < 30
__device__ __forceinline__ void fast_sincos(float v, float& s, float& c) {
    float k = rintf(v * 0.3183098861837907f);
    float r = fmaf(-k, 3.14159274101257f, v);
    r = fmaf(-k, -8.742277657347586e-8f, r);
    float r2 = r * r;
    float ps = fmaf(r2, -2.5052108385e-8f, 2.7557319224e-6f);
    ps = fmaf(r2, ps, -1.9841269841e-4f);
    ps = fmaf(r2, ps, 8.3333333333e-3f);
    ps = fmaf(r2, ps, -1.6666666667e-1f);
    ps = fmaf(r2, ps, 1.0f);
    float pc = fmaf(r2, -2.7557319224e-7f, 2.4801587302e-5f);
    pc = fmaf(r2, pc, -1.3888888889e-3f);
    pc = fmaf(r2, pc, 4.1666666667e-2f);
    pc = fmaf(r2, pc, -0.5f);
    float sg = (((int)k) & 1) ? -1.0f : 1.0f;
    s = r * ps * sg;
    c = fmaf(r2, pc, 1.0f) * sg;
}

// ---------------- LayerNorm reduce helper (block over one 512-row) ----------
__device__ __forceinline__ void ln_stats_block(float2 v, float& mean, float& rstd) {
    float s  = v.x + v.y;
    float sq = v.x * v.x + v.y * v.y;
    __shared__ float ss[8], sqq[8];
    __shared__ float sm, sr;
    #pragma unroll
    for (int o = 16; o > 0; o >>= 1) {
        s  += __shfl_down_sync(0xffffffffu, s,  o);
        sq += __shfl_down_sync(0xffffffffu, sq, o);
    }
    int lane = threadIdx.x & 31, wid = threadIdx.x >> 5;
    if (lane == 0) { ss[wid] = s; sqq[wid] = sq; }
    __syncthreads();
    if (wid == 0) {
        float a = (lane < 8) ? ss[lane]  : 0.f;
        float q = (lane < 8) ? sqq[lane] : 0.f;
        #pragma unroll
        for (int o = 4; o > 0; o >>= 1) {
            a += __shfl_down_sync(0xffffffffu, a, o);
            q += __shfl_down_sync(0xffffffffu, q, o);
        }
        if (lane == 0) {
            float m = a * (1.0f / 512.f);
            sm = m;
            sr = rsqrtf(q * (1.0f / 512.f) - m * m + 1e-5f);
        }
    }
    __syncthreads();
    mean = sm;
    rstd = sr;
}

// Stats-only LN pass for stage 1: writes float2(mean, rstd) per row
__global__ void ln_stats(const float* __restrict__ x, float2* __restrict__ st)
{
    int row = blockIdx.x;
    float2 v = ((const float2*)(x + (size_t)row * C_))[threadIdx.x];
    float m, r;
    ln_stats_block(v, m, r);
    if (threadIdx.x == 0) st[row] = make_float2(m, r);
}

// ---- packs: coef (2,O,512,3)->fp16 (O x 3072, k=i*6+g*2+trig); lw -> fp16
__global__ void pack_stage(const float* __restrict__ coef, const float* __restrict__ lw,
                           __half* __restrict__ Cd, __half* __restrict__ Wd,
                           int O, int LWTOT)
{
    int idx = blockIdx.x * blockDim.x + threadIdx.x;
    int nc = O * KF;
    if (idx < nc) {
        int o = idx / KF, r = idx % KF;
        int i = r / 6, rr = r % 6, g = rr >> 1, trig = rr & 1;
        Cd[idx] = __float2half_rn(coef[(((size_t)trig * O + o) * 512 + i) * G_ + g]);
    } else {
        int j = idx - nc;
        if (j < LWTOT) Wd[j] = __float2half_rn(lw[j]);
    }
}

// ---- token features: fused LN-apply (stats) + expansion, transposed read ----
__global__ __launch_bounds__(256)
void feat_tok(const float* __restrict__ x, const float2* __restrict__ st,
              const float* __restrict__ lnw, const float* __restrict__ lnb,
              __half* __restrict__ F)
{
    __shared__ float s[256 * 33];
    __shared__ float2 sst[256];
    const int t = threadIdx.x;
    const int c0 = blockIdx.x * 32, i0 = blockIdx.y * 256, b = blockIdx.z;
    #pragma unroll
    for (int it = 0; it < 8; it++) {
        int r = it * 32 + (t >> 3), cc = (t & 7) * 4;
        float4 v = *(const float4*)(x + ((size_t)(b * T_ + i0 + r)) * C_ + c0 + cc);
        s[r * 33 + cc] = v.x; s[r * 33 + cc + 1] = v.y;
        s[r * 33 + cc + 2] = v.z; s[r * 33 + cc + 3] = v.w;
    }
    sst[t] = st[b * T_ + i0 + t];
    __syncthreads();
    const int w = t >> 5, lane = t & 31;
    #pragma unroll
    for (int rep = 0; rep < 4; rep++) {
        const int cl = w * 4 + rep;
        const float wc = lnw[c0 + cl];
        const float bc = lnb[c0 + cl];
        const size_t n = (size_t)(b * C_ + c0 + cl);
        #pragma unroll
        for (int it2 = 0; it2 < 8; it2++) {
            int il = it2 * 32 + lane;
            float2 mr = sst[il];
            float v = (s[il * 33 + cl] - mr.x) * mr.y * wc + bc;
            float s1, c1;
            fast_sincos(v, s1, c1);
            float c2 = fmaf(2.f * c1, c1, -1.f);
            float s2 = 2.f * s1 * c1;
            float c3 = fmaf(2.f * c1, c2, -c1);
            float s3 = fmaf(2.f * c1, s2, -s1);
            size_t base = n * KF + (size_t)(i0 + il) * 6;
            __half2* p = (__half2*)(F + base);
            p[0] = __floats2half2_rn(c1, s1);
            p[1] = __floats2half2_rn(c2, s2);
            p[2] = __floats2half2_rn(c3, s3);
        }
    }
}

// ---------------- channel features: fused LN2 + expansion -----------------
__global__ __launch_bounds__(256)
void feat_ch(const float* __restrict__ x1, const float* __restrict__ w,
             const float* __restrict__ b, __half* __restrict__ F)
{
    int row = blockIdx.x;
    float2 v = ((const float2*)(x1 + (size_t)row * C_))[threadIdx.x];
    float m, r;
    ln_stats_block(v, m, r);
    float2 wv = ((const float2*)w)[threadIdx.x];
    float2 bv = ((const float2*)b)[threadIdx.x];
    float ln0 = (v.x - m) * r * wv.x + bv.x;
    float ln1 = (v.y - m) * r * wv.y + bv.y;
    #pragma unroll
    for (int q = 0; q < 2; q++) {
        float vv = q ? ln1 : ln0;
        int c = threadIdx.x * 2 + q;
        float s1, c1;
        fast_sincos(vv, s1, c1);
        float c2 = fmaf(2.f * c1, c1, -1.f);
        float s2 = 2.f * s1 * c1;
        float c3 = fmaf(2.f * c1, c2, -c1);
        float s3 = fmaf(2.f * c1, s2, -s1);
        size_t base = (size_t)row * KF + (size_t)c * 6;
        __half2* p = (__half2*)(F + base);
        p[0] = __floats2half2_rn(c1, s1);
        p[1] = __floats2half2_rn(c2, s2);
        p[2] = __floats2half2_rn(c3, s3);
    }
}

// ---- fp16 TN GEMM, 3-stage cp.async, CTA 128x128, 256 thr, 2 CTAs/SM ----
// 8 warps in 4x2 grid: warp tile 32x64. A-fragments preloaded for whole chunk.
// MODE 0: fp16 out outH[m*Ntot+n]=D+bias
// MODE 1: m=(b,c), n=t: outF[(b*T+n)*C+c] = res + D + bias
// MODE 2: outF[m*C+n] = res + D + bias
template<int MODE>
__global__ __launch_bounds__(NTHR, 2)
void gemm_std(const __half* __restrict__ A, const __half* __restrict__ Bm,
              const float* __restrict__ bias, const float* __restrict__ res,
              float* __restrict__ outF, __half* __restrict__ outH,
              int K, int Ntot)
{
    extern __shared__ char smem[];
    const uint32_t sbase = smem_u32(smem);
    const int tid = threadIdx.x, wid = tid >> 5, lane = tid & 31;
    const int m0 = blockIdx.y * MT, n0 = blockIdx.x * NT;
    const int wm = wid >> 1, wn = wid & 1;   // 4x2 warp grid

    float acc[2][8][4];
    #pragma unroll
    for (int i = 0; i < 2; i++)
        #pragma unroll
        for (int j = 0; j < 8; j++)
            #pragma unroll
            for (int q = 0; q < 4; q++) acc[i][j][q] = 0.f;

    const int NC = K >> 6;

    auto load_chunk = [&](int kc, int buf) {
        const uint32_t sb = sbase + (uint32_t)buf * SBUF;
        const size_t kcol = (size_t)kc * BK;
        #pragma unroll
        for (int it = 0; it < 4; it++) {
            int u = tid + it * NTHR;
            int r = u >> 3, cch = u & 7;
            uint32_t off = r * 128 + ((cch ^ (r & 7)) << 4);
            cpasync16(sb + off, (const char*)(A + (size_t)(m0 + r) * K + kcol) + cch * 16);
        }
        #pragma unroll
        for (int it = 0; it < 4; it++) {
            int u = tid + it * NTHR;
            int r = u >> 3, cch = u & 7;
            uint32_t off = r * 128 + ((cch ^ (r & 7)) << 4);
            cpasync16(sb + SOFF_B + off, (const char*)(Bm + (size_t)(n0 + r) * K + kcol) + cch * 16);
        }
    };

    load_chunk(0, 0);
    cp_commit();
    if (NC > 1) load_chunk(1, 1);
    cp_commit();

    const int lr = lane & 7, lq = lane >> 3;

    int cbuf = 0, lbuf = 2;
    for (int kc = 0; kc < NC; kc++) {
        cp_wait1();
        __syncthreads();
        const uint32_t sb = sbase + (uint32_t)cbuf * SBUF;
        // preload all A fragments for this chunk
        uint32_t ahc[4][2][4];
        #pragma unroll
        for (int k16 = 0; k16 < 4; k16++) {
            #pragma unroll
            for (int i = 0; i < 2; i++) {
                int row = wm * 32 + i * 16 + lr + (lq & 1) * 8;
                int ch  = (k16 * 2 + (lq >> 1)) ^ (row & 7);
                ldsm4(sb + row * 128 + (ch << 4), ahc[k16][i]);
            }
        }
        #pragma unroll
        for (int k16 = 0; k16 < 4; k16++) {
            #pragma unroll
            for (int jp = 0; jp < 4; jp++) {
                int row = wn * 64 + jp * 16 + lr + (lq >> 1) * 8;
                int ch  = (k16 * 2 + (lq & 1)) ^ (row & 7);
                uint32_t tb[4];
                ldsm4(sb + SOFF_B + row * 128 + (ch << 4), tb);
                #pragma unroll
                for (int i = 0; i < 2; i++) {
                    mma_f16(acc[i][2*jp],   ahc[k16][i], tb);
                    mma_f16(acc[i][2*jp+1], ahc[k16][i], tb + 2);
                }
            }
        }
        int nk = kc + 2;
        if (nk < NC) load_chunk(nk, lbuf);
        cp_commit();
        cbuf = (cbuf + 1 == 3) ? 0 : cbuf + 1;
        lbuf = (lbuf + 1 == 3) ? 0 : lbuf + 1;
    }
    cp_wait0();
    __syncthreads();

    // stage accumulators to smem
    float* stage = (float*)smem;
    {
        const int g = lane >> 2, t2 = (lane & 3) * 2;
        #pragma unroll
        for (int i = 0; i < 2; i++) {
            int row = wm * 32 + i * 16 + g;
            #pragma unroll
            for (int j = 0; j < 8; j++) {
                int col = wn * 64 + j * 8 + t2;
                stage[row * STG_S + col]           = acc[i][j][0];
                stage[row * STG_S + col + 1]       = acc[i][j][1];
                stage[(row + 8) * STG_S + col]     = acc[i][j][2];
                stage[(row + 8) * STG_S + col + 1] = acc[i][j][3];
            }
        }
    }
    __syncthreads();

    if (MODE == 0) {
        for (int u = tid; u < 128 * (NT / 2); u += NTHR) {
            int r = u >> 6;
            int c = (u & 63) * 2;
            float v0 = stage[r * STG_S + c]     + bias[n0 + c];
            float v1 = stage[r * STG_S + c + 1] + bias[n0 + c + 1];
            size_t rowb = (size_t)(m0 + r) * Ntot;
            ((__half2*)(outH + rowb + n0 + c))[0] = __floats2half2_rn(v0, v1);
        }
    } else if (MODE == 1) {
        const int b = m0 >> 9, c0 = m0 & 511;
        for (int nl = wid; nl < NT; nl += 8) {
            int n = n0 + nl;
            float bn = bias[n];
            size_t obase = ((size_t)(b * T_ + n)) * C_ + c0;
            #pragma unroll
            for (int cc = 0; cc < 4; cc++) {
                int c = lane + cc * 32;
                outF[obase + c] = res[obase + c] + stage[c * STG_S + nl] + bn;
            }
        }
    } else {
        for (int u = tid; u < 128 * (NT / 4); u += NTHR) {
            int r = u >> 5;
            int c = (u & 31) * 4;
            size_t base = (size_t)(m0 + r) * C_ + n0 + c;
            float4 rv = *(const float4*)(res + base);
            float4 ov;
            ov.x = rv.x + stage[r * STG_S + c]     + bias[n0 + c];
            ov.y = rv.y + stage[r * STG_S + c + 1] + bias[n0 + c + 1];
            ov.z = rv.z + stage[r * STG_S + c + 2] + bias[n0 + c + 2];
            ov.w = rv.w + stage[r * STG_S + c + 3] + bias[n0 + c + 3];
            *(float4*)(outF + base) = ov;
        }
    }
}

// ---------------- launch ----------------
extern "C" void kernel_launch(void* const* d_in, const int* in_sizes, int n_in,
                              void* d_out, int out_size)
{
    const float* x        = (const float*)d_in[0];
    const float* ln1_w    = (const float*)d_in[1];
    const float* ln1_b    = (const float*)d_in[2];
    const float* tok_coef = (const float*)d_in[3];
    const float* tok_kb   = (const float*)d_in[4];
    const float* tok_lw   = (const float*)d_in[5];
    const float* tok_lb   = (const float*)d_in[6];
    const float* ln2_w    = (const float*)d_in[7];
    const float* ln2_b    = (const float*)d_in[8];
    const float* ch_coef  = (const float*)d_in[9];
    const float* ch_kb    = (const float*)d_in[10];
    const float* ch_lw    = (const float*)d_in[11];
    const float* ch_lb    = (const float*)d_in[12];
    float* out = (float*)d_out;

    char* base;
    cudaGetSymbolAddress((void**)&base, g_scratch);
    __half* pF  = (__half*)(base + OFF_F);
    __half* pZ  = (__half*)(base + OFF_Z);
    __half* pCT = (__half*)(base + OFF_CT);
    __half* pWT = (__half*)(base + OFF_WT);
    __half* pCC = (__half*)(base + OFF_CC);
    __half* pWC = (__half*)(base + OFF_WC);
    float2* pSt = (float2*)(base + OFF_ST);
    float*  pX1 = (float*)(base + OFF_X1);

    cudaFuncSetAttribute(gemm_std<0>, cudaFuncAttributeMaxDynamicSharedMemorySize, SMEMS_SZ);
    cudaFuncSetAttribute(gemm_std<1>, cudaFuncAttributeMaxDynamicSharedMemorySize, SMEMS_SZ);
    cudaFuncSetAttribute(gemm_std<2>, cudaFuncAttributeMaxDynamicSharedMemorySize, SMEMS_SZ);

    // ---- token mixing ----
    ln_stats<<<B_ * T_, 256>>>(x, pSt);
    pack_stage<<<(TD_ * KF + T_ * TD_ + 255) / 256, 256>>>(
        tok_coef, tok_lw, pCT, pWT, TD_, T_ * TD_);
    feat_tok<<<dim3(C_ / 32, T_ / 256, B_), 256>>>(x, pSt, ln1_w, ln1_b, pF);
    // z (M x 256) = F * coef^T + kbias  (fp16 out)
    gemm_std<0><<<dim3(TD_ / NT, MROWS / MT), NTHR, SMEMS_SZ>>>(
        pF, pCT, tok_kb, nullptr, nullptr, pZ, KF, 256);
    // x1 = x + transpose(z * lw^T + lb)
    gemm_std<1><<<dim3(T_ / NT, MROWS / MT), NTHR, SMEMS_SZ>>>(
        pZ, pWT, tok_lb, x, pX1, nullptr, 256, 0);

    // ---- channel mixing ----
    pack_stage<<<(1024 * KF + 512 * 1024 + 255) / 256, 256>>>(
        ch_coef, ch_lw, pCC, pWC, 1024, 512 * 1024);
    feat_ch<<<B_ * T_, 256>>>(pX1, ln2_w, ln2_b, pF);
    // z2 (M x 1024) = F * coef^T + kbias  (fp16 out)
    gemm_std<0><<<dim3(1024 / NT, MROWS / MT), NTHR, SMEMS_SZ>>>(
        pF, pCC, ch_kb, nullptr, nullptr, pZ, KF, 1024);
    // out = x1 + (z2 * lw^T + lb)
    gemm_std<2><<<dim3(C_ / NT, MROWS / MT), NTHR, SMEMS_SZ>>>(
        pZ, pWC, ch_lb, pX1, out, nullptr, 1024, 512);
}

// round 13
// speedup vs baseline: 1.0666x; 1.0666x over previous
#include <cuda_runtime.h>
#include <cuda_fp16.h>
#include <math.h>
#include <stdint.h>

#define B_  32
#define T_  512
#define C_  512
#define TD_ 256
#define G_  3
#define MROWS 16384
#define KF  3072               // feature K (single stream)

#define MT 128
#define NT 128
#define BK 64
#define NTHR 256
// fp16 gemm smem: per stage A 16K | B 16K = 32K, 3 stages -> 96KB (2 CTA/SM)
#define SOFF_B 16384u
#define SBUF 32768u
#define SMEMS_SZ (3 * 32768)
#define STG_S 133

// ---------------- scratch arena ----------------
#define MB (1024ull * 1024ull)
#define OFF_F     0ull             // features fp16 (16384 x 3072) 96MB (both stages)
#define OFF_Z     (96ull  * MB)    // z fp16: tok 8MB / ch 32MB
#define OFF_CT    (160ull * MB)    // tok coef (256 x 3072) 1.5MB
#define OFF_WT    (162ull * MB)    // tok lw fp16 (512 x 256) 0.25MB
#define OFF_CC    (164ull * MB)    // ch coef (1024 x 3072) 6MB
#define OFF_WC    (172ull * MB)    // ch lw fp16 (512 x 1024) 1MB
#define OFF_ST    (174ull * MB)    // LN1 stats float2 per row (128KB)
#define OFF_X1    (206ull * MB)    // x1 fp32 32MB
__device__ __align__(256) char g_scratch[240ull * MB];

// ---------------- PTX helpers ----------------
__device__ __forceinline__ uint32_t smem_u32(const void* p) {
    uint32_t a;
    asm("{ .reg .u64 t; cvta.to.shared.u64 t, %1; cvt.u32.u64 %0, t; }" : "=r"(a) : "l"(p));
    return a;
}
__device__ __forceinline__ void cpasync16(uint32_t dst, const void* src) {
    asm volatile("cp.async.cg.shared.global [%0], [%1], 16;" :: "r"(dst), "l"(src));
}
__device__ __forceinline__ void cp_commit() { asm volatile("cp.async.commit_group;" ::: "memory"); }
__device__ __forceinline__ void cp_wait0()  { asm volatile("cp.async.wait_group 0;" ::: "memory"); }
__device__ __forceinline__ void cp_wait1()  { asm volatile("cp.async.wait_group 1;" ::: "memory"); }
__device__ __forceinline__ void ldsm4(uint32_t addr, uint32_t r[4]) {
    asm volatile("ldmatrix.sync.aligned.m8n8.x4.shared.b16 {%0,%1,%2,%3}, [%4];"
                 : "=r"(r[0]), "=r"(r[1]), "=r"(r[2]), "=r"(r[3]) : "r"(addr));
}
__device__ __forceinline__ void mma_f16(float d[4], const uint32_t a[4], const uint32_t b[2]) {
    asm volatile(
        "mma.sync.aligned.m16n8k16.row.col.f32.f16.f16.f32 "
        "{%0,%1,%2,%3}, {%4,%5,%6,%7}, {%8,%9}, {%0,%1,%2,%3};"
        : "+f"(d[0]), "+f"(d[1]), "+f"(d[2]), "+f"(d[3])
        : "r"(a[0]), "r"(a[1]), "r"(a[2]), "r"(a[3]), "r"(b[0]), "r"(b[1]));
}
// Polynomial sincos, pure FMA pipe, err < 5e-7 for |v| < 30
__device__ __forceinline__ void fast_sincos(float v, float& s, float& c) {
    float k = rintf(v * 0.3183098861837907f);
    float r = fmaf(-k, 3.14159274101257f, v);
    r = fmaf(-k, -8.742277657347586e-8f, r);
    float r2 = r * r;
    float ps = fmaf(r2, -2.5052108385e-8f, 2.7557319224e-6f);
    ps = fmaf(r2, ps, -1.9841269841e-4f);
    ps = fmaf(r2, ps, 8.3333333333e-3f);
    ps = fmaf(r2, ps, -1.6666666667e-1f);
    ps = fmaf(r2, ps, 1.0f);
    float pc = fmaf(r2, -2.7557319224e-7f, 2.4801587302e-5f);
    pc = fmaf(r2, pc, -1.3888888889e-3f);
    pc = fmaf(r2, pc, 4.1666666667e-2f);
    pc = fmaf(r2, pc, -0.5f);
    float sg = (((int)k) & 1) ? -1.0f : 1.0f;
    s = r * ps * sg;
    c = fmaf(r2, pc, 1.0f) * sg;
}

// ---------------- LayerNorm reduce helper (block over one 512-row) ----------
__device__ __forceinline__ void ln_stats_block(float2 v, float& mean, float& rstd) {
    float s  = v.x + v.y;
    float sq = v.x * v.x + v.y * v.y;
    __shared__ float ss[8], sqq[8];
    __shared__ float sm, sr;
    #pragma unroll
    for (int o = 16; o > 0; o >>= 1) {
        s  += __shfl_down_sync(0xffffffffu, s,  o);
        sq += __shfl_down_sync(0xffffffffu, sq, o);
    }
    int lane = threadIdx.x & 31, wid = threadIdx.x >> 5;
    if (lane == 0) { ss[wid] = s; sqq[wid] = sq; }
    __syncthreads();
    if (wid == 0) {
        float a = (lane < 8) ? ss[lane]  : 0.f;
        float q = (lane < 8) ? sqq[lane] : 0.f;
        #pragma unroll
        for (int o = 4; o > 0; o >>= 1) {
            a += __shfl_down_sync(0xffffffffu, a, o);
            q += __shfl_down_sync(0xffffffffu, q, o);
        }
        if (lane == 0) {
            float m = a * (1.0f / 512.f);
            sm = m;
            sr = rsqrtf(q * (1.0f / 512.f) - m * m + 1e-5f);
        }
    }
    __syncthreads();
    mean = sm;
    rstd = sr;
}

// Stats-only LN pass for stage 1: writes float2(mean, rstd) per row
__global__ void ln_stats(const float* __restrict__ x, float2* __restrict__ st)
{
    int row = blockIdx.x;
    float2 v = ((const float2*)(x + (size_t)row * C_))[threadIdx.x];
    float m, r;
    ln_stats_block(v, m, r);
    if (threadIdx.x == 0) st[row] = make_float2(m, r);
}

// ---- packs: coef (2,O,512,3)->fp16 (O x 3072, k=i*6+g*2+trig); lw -> fp16
__global__ void pack_stage(const float* __restrict__ coef, const float* __restrict__ lw,
                           __half* __restrict__ Cd, __half* __restrict__ Wd,
                           int O, int LWTOT)
{
    int idx = blockIdx.x * blockDim.x + threadIdx.x;
    int nc = O * KF;
    if (idx < nc) {
        int o = idx / KF, r = idx % KF;
        int i = r / 6, rr = r % 6, g = rr >> 1, trig = rr & 1;
        Cd[idx] = __float2half_rn(coef[(((size_t)trig * O + o) * 512 + i) * G_ + g]);
    } else {
        int j = idx - nc;
        if (j < LWTOT) Wd[j] = __float2half_rn(lw[j]);
    }
}

// ---- token features: fused LN-apply (stats) + expansion, transposed read ----
__global__ __launch_bounds__(256)
void feat_tok(const float* __restrict__ x, const float2* __restrict__ st,
              const float* __restrict__ lnw, const float* __restrict__ lnb,
              __half* __restrict__ F)
{
    __shared__ float s[256 * 33];
    __shared__ float2 sst[256];
    const int t = threadIdx.x;
    const int c0 = blockIdx.x * 32, i0 = blockIdx.y * 256, b = blockIdx.z;
    #pragma unroll
    for (int it = 0; it < 8; it++) {
        int r = it * 32 + (t >> 3), cc = (t & 7) * 4;
        float4 v = *(const float4*)(x + ((size_t)(b * T_ + i0 + r)) * C_ + c0 + cc);
        s[r * 33 + cc] = v.x; s[r * 33 + cc + 1] = v.y;
        s[r * 33 + cc + 2] = v.z; s[r * 33 + cc + 3] = v.w;
    }
    sst[t] = st[b * T_ + i0 + t];
    __syncthreads();
    const int w = t >> 5, lane = t & 31;
    #pragma unroll
    for (int rep = 0; rep < 4; rep++) {
        const int cl = w * 4 + rep;
        const float wc = lnw[c0 + cl];
        const float bc = lnb[c0 + cl];
        const size_t n = (size_t)(b * C_ + c0 + cl);
        #pragma unroll
        for (int it2 = 0; it2 < 8; it2++) {
            int il = it2 * 32 + lane;
            float2 mr = sst[il];
            float v = (s[il * 33 + cl] - mr.x) * mr.y * wc + bc;
            float s1, c1;
            fast_sincos(v, s1, c1);
            float c2 = fmaf(2.f * c1, c1, -1.f);
            float s2 = 2.f * s1 * c1;
            float c3 = fmaf(2.f * c1, c2, -c1);
            float s3 = fmaf(2.f * c1, s2, -s1);
            size_t base = n * KF + (size_t)(i0 + il) * 6;
            __half2* p = (__half2*)(F + base);
            p[0] = __floats2half2_rn(c1, s1);
            p[1] = __floats2half2_rn(c2, s2);
            p[2] = __floats2half2_rn(c3, s3);
        }
    }
}

// ---------------- channel features: fused LN2 + expansion -----------------
__global__ __launch_bounds__(256)
void feat_ch(const float* __restrict__ x1, const float* __restrict__ w,
             const float* __restrict__ b, __half* __restrict__ F)
{
    int row = blockIdx.x;
    float2 v = ((const float2*)(x1 + (size_t)row * C_))[threadIdx.x];
    float m, r;
    ln_stats_block(v, m, r);
    float2 wv = ((const float2*)w)[threadIdx.x];
    float2 bv = ((const float2*)b)[threadIdx.x];
    float ln0 = (v.x - m) * r * wv.x + bv.x;
    float ln1 = (v.y - m) * r * wv.y + bv.y;
    #pragma unroll
    for (int q = 0; q < 2; q++) {
        float vv = q ? ln1 : ln0;
        int c = threadIdx.x * 2 + q;
        float s1, c1;
        fast_sincos(vv, s1, c1);
        float c2 = fmaf(2.f * c1, c1, -1.f);
        float s2 = 2.f * s1 * c1;
        float c3 = fmaf(2.f * c1, c2, -c1);
        float s3 = fmaf(2.f * c1, s2, -s1);
        size_t base = (size_t)row * KF + (size_t)c * 6;
        __half2* p = (__half2*)(F + base);
        p[0] = __floats2half2_rn(c1, s1);
        p[1] = __floats2half2_rn(c2, s2);
        p[2] = __floats2half2_rn(c3, s3);
    }
}

// ---- fp16 TN GEMM, 3-stage cp.async, CTA 128x128, 256 thr, 2 CTAs/SM ----
// 8 warps in 4x2 grid: warp tile 32x64. (R11 inner loop — per-k16 interleave)
// MODE 0: fp16 out outH[m*Ntot+n]=D+bias
// MODE 1: m=(b,c), n=t: outF[(b*T+n)*C+c] = res + D + bias
// MODE 2: outF[m*C+n] = res + D + bias
template<int MODE>
__global__ __launch_bounds__(NTHR, 2)
void gemm_std(const __half* __restrict__ A, const __half* __restrict__ Bm,
              const float* __restrict__ bias, const float* __restrict__ res,
              float* __restrict__ outF, __half* __restrict__ outH,
              int K, int Ntot)
{
    extern __shared__ char smem[];
    const uint32_t sbase = smem_u32(smem);
    const int tid = threadIdx.x, wid = tid >> 5, lane = tid & 31;
    const int m0 = blockIdx.y * MT, n0 = blockIdx.x * NT;
    const int wm = wid >> 1, wn = wid & 1;   // 4x2 warp grid

    float acc[2][8][4];
    #pragma unroll
    for (int i = 0; i < 2; i++)
        #pragma unroll
        for (int j = 0; j < 8; j++)
            #pragma unroll
            for (int q = 0; q < 4; q++) acc[i][j][q] = 0.f;

    const int NC = K >> 6;

    auto load_chunk = [&](int kc, int buf) {
        const uint32_t sb = sbase + (uint32_t)buf * SBUF;
        const size_t kcol = (size_t)kc * BK;
        #pragma unroll
        for (int it = 0; it < 4; it++) {
            int u = tid + it * NTHR;
            int r = u >> 3, cch = u & 7;
            uint32_t off = r * 128 + ((cch ^ (r & 7)) << 4);
            cpasync16(sb + off, (const char*)(A + (size_t)(m0 + r) * K + kcol) + cch * 16);
        }
        #pragma unroll
        for (int it = 0; it < 4; it++) {
            int u = tid + it * NTHR;
            int r = u >> 3, cch = u & 7;
            uint32_t off = r * 128 + ((cch ^ (r & 7)) << 4);
            cpasync16(sb + SOFF_B + off, (const char*)(Bm + (size_t)(n0 + r) * K + kcol) + cch * 16);
        }
    };

    load_chunk(0, 0);
    cp_commit();
    if (NC > 1) load_chunk(1, 1);
    cp_commit();

    const int lr = lane & 7, lq = lane >> 3;

    int cbuf = 0, lbuf = 2;
    for (int kc = 0; kc < NC; kc++) {
        cp_wait1();
        __syncthreads();
        const uint32_t sb = sbase + (uint32_t)cbuf * SBUF;
        #pragma unroll
        for (int k16 = 0; k16 < 4; k16++) {
            uint32_t ah[2][4];
            #pragma unroll
            for (int i = 0; i < 2; i++) {
                int row = wm * 32 + i * 16 + lr + (lq & 1) * 8;
                int ch  = (k16 * 2 + (lq >> 1)) ^ (row & 7);
                ldsm4(sb + row * 128 + (ch << 4), ah[i]);
            }
            #pragma unroll
            for (int jp = 0; jp < 4; jp++) {
                int row = wn * 64 + jp * 16 + lr + (lq >> 1) * 8;
                int ch  = (k16 * 2 + (lq & 1)) ^ (row & 7);
                uint32_t tb[4];
                ldsm4(sb + SOFF_B + row * 128 + (ch << 4), tb);
                #pragma unroll
                for (int i = 0; i < 2; i++) {
                    mma_f16(acc[i][2*jp],   ah[i], tb);
                    mma_f16(acc[i][2*jp+1], ah[i], tb + 2);
                }
            }
        }
        int nk = kc + 2;
        if (nk < NC) load_chunk(nk, lbuf);
        cp_commit();
        cbuf = (cbuf + 1 == 3) ? 0 : cbuf + 1;
        lbuf = (lbuf + 1 == 3) ? 0 : lbuf + 1;
    }
    cp_wait0();
    __syncthreads();

    // stage accumulators to smem
    float* stage = (float*)smem;
    {
        const int g = lane >> 2, t2 = (lane & 3) * 2;
        #pragma unroll
        for (int i = 0; i < 2; i++) {
            int row = wm * 32 + i * 16 + g;
            #pragma unroll
            for (int j = 0; j < 8; j++) {
                int col = wn * 64 + j * 8 + t2;
                stage[row * STG_S + col]           = acc[i][j][0];
                stage[row * STG_S + col + 1]       = acc[i][j][1];
                stage[(row + 8) * STG_S + col]     = acc[i][j][2];
                stage[(row + 8) * STG_S + col + 1] = acc[i][j][3];
            }
        }
    }
    __syncthreads();

    if (MODE == 0) {
        for (int u = tid; u < 128 * (NT / 2); u += NTHR) {
            int r = u >> 6;
            int c = (u & 63) * 2;
            float v0 = stage[r * STG_S + c]     + bias[n0 + c];
            float v1 = stage[r * STG_S + c + 1] + bias[n0 + c + 1];
            size_t rowb = (size_t)(m0 + r) * Ntot;
            ((__half2*)(outH + rowb + n0 + c))[0] = __floats2half2_rn(v0, v1);
        }
    } else if (MODE == 1) {
        const int b = m0 >> 9, c0 = m0 & 511;
        for (int nl = wid; nl < NT; nl += 8) {
            int n = n0 + nl;
            float bn = bias[n];
            size_t obase = ((size_t)(b * T_ + n)) * C_ + c0;
            #pragma unroll
            for (int cc = 0; cc < 4; cc++) {
                int c = lane + cc * 32;
                outF[obase + c] = res[obase + c] + stage[c * STG_S + nl] + bn;
            }
        }
    } else {
        for (int u = tid; u < 128 * (NT / 4); u += NTHR) {
            int r = u >> 5;
            int c = (u & 31) * 4;
            size_t base = (size_t)(m0 + r) * C_ + n0 + c;
            float4 rv = *(const float4*)(res + base);
            float4 ov;
            ov.x = rv.x + stage[r * STG_S + c]     + bias[n0 + c];
            ov.y = rv.y + stage[r * STG_S + c + 1] + bias[n0 + c + 1];
            ov.z = rv.z + stage[r * STG_S + c + 2] + bias[n0 + c + 2];
            ov.w = rv.w + stage[r * STG_S + c + 3] + bias[n0 + c + 3];
            *(float4*)(outF + base) = ov;
        }
    }
}

// ---------------- launch ----------------
extern "C" void kernel_launch(void* const* d_in, const int* in_sizes, int n_in,
                              void* d_out, int out_size)
{
    const float* x        = (const float*)d_in[0];
    const float* ln1_w    = (const float*)d_in[1];
    const float* ln1_b    = (const float*)d_in[2];
    const float* tok_coef = (const float*)d_in[3];
    const float* tok_kb   = (const float*)d_in[4];
    const float* tok_lw   = (const float*)d_in[5];
    const float* tok_lb   = (const float*)d_in[6];
    const float* ln2_w    = (const float*)d_in[7];
    const float* ln2_b    = (const float*)d_in[8];
    const float* ch_coef  = (const float*)d_in[9];
    const float* ch_kb    = (const float*)d_in[10];
    const float* ch_lw    = (const float*)d_in[11];
    const float* ch_lb    = (const float*)d_in[12];
    float* out = (float*)d_out;

    char* base;
    cudaGetSymbolAddress((void**)&base, g_scratch);
    __half* pF  = (__half*)(base + OFF_F);
    __half* pZ  = (__half*)(base + OFF_Z);
    __half* pCT = (__half*)(base + OFF_CT);
    __half* pWT = (__half*)(base + OFF_WT);
    __half* pCC = (__half*)(base + OFF_CC);
    __half* pWC = (__half*)(base + OFF_WC);
    float2* pSt = (float2*)(base + OFF_ST);
    float*  pX1 = (float*)(base + OFF_X1);

    cudaFuncSetAttribute(gemm_std<0>, cudaFuncAttributeMaxDynamicSharedMemorySize, SMEMS_SZ);
    cudaFuncSetAttribute(gemm_std<1>, cudaFuncAttributeMaxDynamicSharedMemorySize, SMEMS_SZ);
    cudaFuncSetAttribute(gemm_std<2>, cudaFuncAttributeMaxDynamicSharedMemorySize, SMEMS_SZ);

    // ---- token mixing ----
    ln_stats<<<B_ * T_, 256>>>(x, pSt);
    pack_stage<<<(TD_ * KF + T_ * TD_ + 255) / 256, 256>>>(
        tok_coef, tok_lw, pCT, pWT, TD_, T_ * TD_);
    feat_tok<<<dim3(C_ / 32, T_ / 256, B_), 256>>>(x, pSt, ln1_w, ln1_b, pF);
    // z (M x 256) = F * coef^T + kbias  (fp16 out)
    gemm_std<0><<<dim3(TD_ / NT, MROWS / MT), NTHR, SMEMS_SZ>>>(
        pF, pCT, tok_kb, nullptr, nullptr, pZ, KF, 256);
    // x1 = x + transpose(z * lw^T + lb)
    gemm_std<1><<<dim3(T_ / NT, MROWS / MT), NTHR, SMEMS_SZ>>>(
        pZ, pWT, tok_lb, x, pX1, nullptr, 256, 0);

    // ---- channel mixing ----
    pack_stage<<<(1024 * KF + 512 * 1024 + 255) / 256, 256>>>(
        ch_coef, ch_lw, pCC, pWC, 1024, 512 * 1024);
    feat_ch<<<B_ * T_, 256>>>(pX1, ln2_w, ln2_b, pF);
    // z2 (M x 1024) = F * coef^T + kbias  (fp16 out)
    gemm_std<0><<<dim3(1024 / NT, MROWS / MT), NTHR, SMEMS_SZ>>>(
        pF, pCC, ch_kb, nullptr, nullptr, pZ, KF, 1024);
    // out = x1 + (z2 * lw^T + lb)
    gemm_std<2><<<dim3(C_ / NT, MROWS / MT), NTHR, SMEMS_SZ>>>(
        pZ, pWC, ch_lb, pX1, out, nullptr, 1024, 512);
}

// round 14
// speedup vs baseline: 1.3887x; 1.3020x over previous
#include <cuda_runtime.h>
#include <cuda_fp16.h>
#include <math.h>
#include <stdint.h>

#define B_  32
#define T_  512
#define C_  512
#define TD_ 256
#define G_  3
#define MROWS 16384
#define KF  3072               // feature K (single stream)

#define MT 128
#define NT 128
#define BK 64
#define NTHR 256
// fp16 gemm smem: per stage A 16K | B 16K = 32K, 3 stages -> 96KB (2 CTA/SM)
#define SOFF_B 16384u
#define SBUF 32768u
#define SMEMS_SZ (3 * 32768)
#define STG_S 133

// ---------------- scratch arena ----------------
#define MB (1024ull * 1024ull)
#define OFF_F     0ull             // features fp16 (16384 x 3072) 96MB (both stages)
#define OFF_Z     (96ull  * MB)    // tok z fp16 (16384 x 256) 8MB
#define OFF_CT    (104ull * MB)    // tok coef (256 x 3072) 1.5MB
#define OFF_WT    (106ull * MB)    // tok lw fp16 (512 x 256) 0.25MB
#define OFF_CP    (108ull * MB)    // ch coef o-major (1024 x 3072) 6MB
#define OFF_CT2   (114ull * MB)    // ch coef k-major (3072 x 1024) 6MB
#define OFF_LW16  (120ull * MB)    // ch lw fp16 (512 x 1024) 1MB
#define OFF_W2    (122ull * MB)    // W2 = lw@C fp16 (512 x 3072) 3MB
#define OFF_B2    (125ull * MB)    // bias2 fp32 (512) 2KB
#define OFF_ST    (126ull * MB)    // LN1 stats float2 per row (128KB)
#define OFF_X1    (128ull * MB)    // x1 fp32 32MB
__device__ __align__(256) char g_scratch[160ull * MB];

// ---------------- PTX helpers ----------------
__device__ __forceinline__ uint32_t smem_u32(const void* p) {
    uint32_t a;
    asm("{ .reg .u64 t; cvta.to.shared.u64 t, %1; cvt.u32.u64 %0, t; }" : "=r"(a) : "l"(p));
    return a;
}
__device__ __forceinline__ void cpasync16(uint32_t dst, const void* src) {
    asm volatile("cp.async.cg.shared.global [%0], [%1], 16;" :: "r"(dst), "l"(src));
}
__device__ __forceinline__ void cp_commit() { asm volatile("cp.async.commit_group;" ::: "memory"); }
__device__ __forceinline__ void cp_wait0()  { asm volatile("cp.async.wait_group 0;" ::: "memory"); }
__device__ __forceinline__ void cp_wait1()  { asm volatile("cp.async.wait_group 1;" ::: "memory"); }
__device__ __forceinline__ void ldsm4(uint32_t addr, uint32_t r[4]) {
    asm volatile("ldmatrix.sync.aligned.m8n8.x4.shared.b16 {%0,%1,%2,%3}, [%4];"
                 : "=r"(r[0]), "=r"(r[1]), "=r"(r[2]), "=r"(r[3]) : "r"(addr));
}
__device__ __forceinline__ void mma_f16(float d[4], const uint32_t a[4], const uint32_t b[2]) {
    asm volatile(
        "mma.sync.aligned.m16n8k16.row.col.f32.f16.f16.f32 "
        "{%0,%1,%2,%3}, {%4,%5,%6,%7}, {%8,%9}, {%0,%1,%2,%3};"
        : "+f"(d[0]), "+f"(d[1]), "+f"(d[2]), "+f"(d[3])
        : "r"(a[0]), "r"(a[1]), "r"(a[2]), "r"(a[3]), "r"(b[0]), "r"(b[1]));
}
// Polynomial sincos, pure FMA pipe, err < 5e-7 for |v| < 30
__device__ __forceinline__ void fast_sincos(float v, float& s, float& c) {
    float k = rintf(v * 0.3183098861837907f);
    float r = fmaf(-k, 3.14159274101257f, v);
    r = fmaf(-k, -8.742277657347586e-8f, r);
    float r2 = r * r;
    float ps = fmaf(r2, -2.5052108385e-8f, 2.7557319224e-6f);
    ps = fmaf(r2, ps, -1.9841269841e-4f);
    ps = fmaf(r2, ps, 8.3333333333e-3f);
    ps = fmaf(r2, ps, -1.6666666667e-1f);
    ps = fmaf(r2, ps, 1.0f);
    float pc = fmaf(r2, -2.7557319224e-7f, 2.4801587302e-5f);
    pc = fmaf(r2, pc, -1.3888888889e-3f);
    pc = fmaf(r2, pc, 4.1666666667e-2f);
    pc = fmaf(r2, pc, -0.5f);
    float sg = (((int)k) & 1) ? -1.0f : 1.0f;
    s = r * ps * sg;
    c = fmaf(r2, pc, 1.0f) * sg;
}

// ---------------- LayerNorm reduce helper (block over one 512-row) ----------
__device__ __forceinline__ void ln_stats_block(float2 v, float& mean, float& rstd) {
    float s  = v.x + v.y;
    float sq = v.x * v.x + v.y * v.y;
    __shared__ float ss[8], sqq[8];
    __shared__ float sm, sr;
    #pragma unroll
    for (int o = 16; o > 0; o >>= 1) {
        s  += __shfl_down_sync(0xffffffffu, s,  o);
        sq += __shfl_down_sync(0xffffffffu, sq, o);
    }
    int lane = threadIdx.x & 31, wid = threadIdx.x >> 5;
    if (lane == 0) { ss[wid] = s; sqq[wid] = sq; }
    __syncthreads();
    if (wid == 0) {
        float a = (lane < 8) ? ss[lane]  : 0.f;
        float q = (lane < 8) ? sqq[lane] : 0.f;
        #pragma unroll
        for (int o = 4; o > 0; o >>= 1) {
            a += __shfl_down_sync(0xffffffffu, a, o);
            q += __shfl_down_sync(0xffffffffu, q, o);
        }
        if (lane == 0) {
            float m = a * (1.0f / 512.f);
            sm = m;
            sr = rsqrtf(q * (1.0f / 512.f) - m * m + 1e-5f);
        }
    }
    __syncthreads();
    mean = sm;
    rstd = sr;
}

// Stats-only LN pass for stage 1
__global__ void ln_stats(const float* __restrict__ x, float2* __restrict__ st)
{
    int row = blockIdx.x;
    float2 v = ((const float2*)(x + (size_t)row * C_))[threadIdx.x];
    float m, r;
    ln_stats_block(v, m, r);
    if (threadIdx.x == 0) st[row] = make_float2(m, r);
}

// ---- packs: coef (2,O,512,3)->fp16 (O x 3072, k=i*6+g*2+trig); lw -> fp16
__global__ void pack_stage(const float* __restrict__ coef, const float* __restrict__ lw,
                           __half* __restrict__ Cd, __half* __restrict__ Wd,
                           int O, int LWTOT)
{
    int idx = blockIdx.x * blockDim.x + threadIdx.x;
    int nc = O * KF;
    if (idx < nc) {
        int o = idx / KF, r = idx % KF;
        int i = r / 6, rr = r % 6, g = rr >> 1, trig = rr & 1;
        Cd[idx] = __float2half_rn(coef[(((size_t)trig * O + o) * 512 + i) * G_ + g]);
    } else {
        int j = idx - nc;
        if (j < LWTOT) Wd[j] = __float2half_rn(lw[j]);
    }
}

// ---- transpose ch coef: Cp (1024 o x 3072 k) -> Ct (3072 k x 1024 o) ----
__global__ __launch_bounds__(256)
void transpose_ch(const __half* __restrict__ Cp, __half* __restrict__ Ct)
{
    __shared__ __half s[32][36];
    int k0 = blockIdx.x * 32, o0 = blockIdx.y * 32;
    int r = threadIdx.x >> 3, c4 = (threadIdx.x & 7) * 4;
    *(uint2*)&s[r][c4] = *(const uint2*)(Cp + (size_t)(o0 + r) * KF + k0 + c4);
    __syncthreads();
    __half tmp[4];
    tmp[0] = s[c4][r]; tmp[1] = s[c4 + 1][r];
    tmp[2] = s[c4 + 2][r]; tmp[3] = s[c4 + 3][r];
    *(uint2*)(Ct + (size_t)(k0 + r) * 1024 + o0 + c4) = *(uint2*)tmp;
}

// ---- bias2[c] = lb[c] + sum_o kb[o]*lw[c,o]  (warp per c) ----
__global__ void bias2_kernel(const float* __restrict__ kb, const float* __restrict__ lw,
                             const float* __restrict__ lb, float* __restrict__ b2)
{
    int c = blockIdx.x * 8 + (threadIdx.x >> 5);
    int lane = threadIdx.x & 31;
    const float* row = lw + (size_t)c * 1024;
    float s = 0.f;
    #pragma unroll 8
    for (int o = lane; o < 1024; o += 32) s += kb[o] * row[o];
    #pragma unroll
    for (int off = 16; off; off >>= 1) s += __shfl_down_sync(0xffffffffu, s, off);
    if (lane == 0) b2[c] = lb[c] + s;
}

// ---- token features: fused LN-apply (stats) + expansion, transposed read ----
__global__ __launch_bounds__(256)
void feat_tok(const float* __restrict__ x, const float2* __restrict__ st,
              const float* __restrict__ lnw, const float* __restrict__ lnb,
              __half* __restrict__ F)
{
    __shared__ float s[256 * 33];
    __shared__ float2 sst[256];
    const int t = threadIdx.x;
    const int c0 = blockIdx.x * 32, i0 = blockIdx.y * 256, b = blockIdx.z;
    #pragma unroll
    for (int it = 0; it < 8; it++) {
        int r = it * 32 + (t >> 3), cc = (t & 7) * 4;
        float4 v = *(const float4*)(x + ((size_t)(b * T_ + i0 + r)) * C_ + c0 + cc);
        s[r * 33 + cc] = v.x; s[r * 33 + cc + 1] = v.y;
        s[r * 33 + cc + 2] = v.z; s[r * 33 + cc + 3] = v.w;
    }
    sst[t] = st[b * T_ + i0 + t];
    __syncthreads();
    const int w = t >> 5, lane = t & 31;
    #pragma unroll
    for (int rep = 0; rep < 4; rep++) {
        const int cl = w * 4 + rep;
        const float wc = lnw[c0 + cl];
        const float bc = lnb[c0 + cl];
        const size_t n = (size_t)(b * C_ + c0 + cl);
        #pragma unroll
        for (int it2 = 0; it2 < 8; it2++) {
            int il = it2 * 32 + lane;
            float2 mr = sst[il];
            float v = (s[il * 33 + cl] - mr.x) * mr.y * wc + bc;
            float s1, c1;
            fast_sincos(v, s1, c1);
            float c2 = fmaf(2.f * c1, c1, -1.f);
            float s2 = 2.f * s1 * c1;
            float c3 = fmaf(2.f * c1, c2, -c1);
            float s3 = fmaf(2.f * c1, s2, -s1);
            size_t base = n * KF + (size_t)(i0 + il) * 6;
            __half2* p = (__half2*)(F + base);
            p[0] = __floats2half2_rn(c1, s1);
            p[1] = __floats2half2_rn(c2, s2);
            p[2] = __floats2half2_rn(c3, s3);
        }
    }
}

// ---------------- channel features: fused LN2 + expansion -----------------
__global__ __launch_bounds__(256)
void feat_ch(const float* __restrict__ x1, const float* __restrict__ w,
             const float* __restrict__ b, __half* __restrict__ F)
{
    int row = blockIdx.x;
    float2 v = ((const float2*)(x1 + (size_t)row * C_))[threadIdx.x];
    float m, r;
    ln_stats_block(v, m, r);
    float2 wv = ((const float2*)w)[threadIdx.x];
    float2 bv = ((const float2*)b)[threadIdx.x];
    float ln0 = (v.x - m) * r * wv.x + bv.x;
    float ln1 = (v.y - m) * r * wv.y + bv.y;
    #pragma unroll
    for (int q = 0; q < 2; q++) {
        float vv = q ? ln1 : ln0;
        int c = threadIdx.x * 2 + q;
        float s1, c1;
        fast_sincos(vv, s1, c1);
        float c2 = fmaf(2.f * c1, c1, -1.f);
        float s2 = 2.f * s1 * c1;
        float c3 = fmaf(2.f * c1, c2, -c1);
        float s3 = fmaf(2.f * c1, s2, -s1);
        size_t base = (size_t)row * KF + (size_t)c * 6;
        __half2* p = (__half2*)(F + base);
        p[0] = __floats2half2_rn(c1, s1);
        p[1] = __floats2half2_rn(c2, s2);
        p[2] = __floats2half2_rn(c3, s3);
    }
}

// ---- fp16 TN GEMM, 3-stage cp.async, CTA 128x128, 256 thr, 2 CTAs/SM ----
// 8 warps in 4x2 grid: warp tile 32x64.
// MODE 0: fp16 out outH[m*Ntot+n]=D+bias (bias may be null)
// MODE 1: m=(b,c), n=t: outF[(b*T+n)*C+c] = res + D + bias
// MODE 2: outF[m*C+n] = res + D + bias
template<int MODE>
__global__ __launch_bounds__(NTHR, 2)
void gemm_std(const __half* __restrict__ A, const __half* __restrict__ Bm,
              const float* __restrict__ bias, const float* __restrict__ res,
              float* __restrict__ outF, __half* __restrict__ outH,
              int K, int Ntot)
{
    extern __shared__ char smem[];
    const uint32_t sbase = smem_u32(smem);
    const int tid = threadIdx.x, wid = tid >> 5, lane = tid & 31;
    const int m0 = blockIdx.y * MT, n0 = blockIdx.x * NT;
    const int wm = wid >> 1, wn = wid & 1;   // 4x2 warp grid

    float acc[2][8][4];
    #pragma unroll
    for (int i = 0; i < 2; i++)
        #pragma unroll
        for (int j = 0; j < 8; j++)
            #pragma unroll
            for (int q = 0; q < 4; q++) acc[i][j][q] = 0.f;

    const int NC = K >> 6;

    auto load_chunk = [&](int kc, int buf) {
        const uint32_t sb = sbase + (uint32_t)buf * SBUF;
        const size_t kcol = (size_t)kc * BK;
        #pragma unroll
        for (int it = 0; it < 4; it++) {
            int u = tid + it * NTHR;
            int r = u >> 3, cch = u & 7;
            uint32_t off = r * 128 + ((cch ^ (r & 7)) << 4);
            cpasync16(sb + off, (const char*)(A + (size_t)(m0 + r) * K + kcol) + cch * 16);
        }
        #pragma unroll
        for (int it = 0; it < 4; it++) {
            int u = tid + it * NTHR;
            int r = u >> 3, cch = u & 7;
            uint32_t off = r * 128 + ((cch ^ (r & 7)) << 4);
            cpasync16(sb + SOFF_B + off, (const char*)(Bm + (size_t)(n0 + r) * K + kcol) + cch * 16);
        }
    };

    load_chunk(0, 0);
    cp_commit();
    if (NC > 1) load_chunk(1, 1);
    cp_commit();

    const int lr = lane & 7, lq = lane >> 3;

    int cbuf = 0, lbuf = 2;
    for (int kc = 0; kc < NC; kc++) {
        cp_wait1();
        __syncthreads();
        const uint32_t sb = sbase + (uint32_t)cbuf * SBUF;
        #pragma unroll
        for (int k16 = 0; k16 < 4; k16++) {
            uint32_t ah[2][4];
            #pragma unroll
            for (int i = 0; i < 2; i++) {
                int row = wm * 32 + i * 16 + lr + (lq & 1) * 8;
                int ch  = (k16 * 2 + (lq >> 1)) ^ (row & 7);
                ldsm4(sb + row * 128 + (ch << 4), ah[i]);
            }
            #pragma unroll
            for (int jp = 0; jp < 4; jp++) {
                int row = wn * 64 + jp * 16 + lr + (lq >> 1) * 8;
                int ch  = (k16 * 2 + (lq & 1)) ^ (row & 7);
                uint32_t tb[4];
                ldsm4(sb + SOFF_B + row * 128 + (ch << 4), tb);
                #pragma unroll
                for (int i = 0; i < 2; i++) {
                    mma_f16(acc[i][2*jp],   ah[i], tb);
                    mma_f16(acc[i][2*jp+1], ah[i], tb + 2);
                }
            }
        }
        int nk = kc + 2;
        if (nk < NC) load_chunk(nk, lbuf);
        cp_commit();
        cbuf = (cbuf + 1 == 3) ? 0 : cbuf + 1;
        lbuf = (lbuf + 1 == 3) ? 0 : lbuf + 1;
    }
    cp_wait0();
    __syncthreads();

    // stage accumulators to smem
    float* stage = (float*)smem;
    {
        const int g = lane >> 2, t2 = (lane & 3) * 2;
        #pragma unroll
        for (int i = 0; i < 2; i++) {
            int row = wm * 32 + i * 16 + g;
            #pragma unroll
            for (int j = 0; j < 8; j++) {
                int col = wn * 64 + j * 8 + t2;
                stage[row * STG_S + col]           = acc[i][j][0];
                stage[row * STG_S + col + 1]       = acc[i][j][1];
                stage[(row + 8) * STG_S + col]     = acc[i][j][2];
                stage[(row + 8) * STG_S + col + 1] = acc[i][j][3];
            }
        }
    }
    __syncthreads();

    if (MODE == 0) {
        for (int u = tid; u < 128 * (NT / 2); u += NTHR) {
            int r = u >> 6;
            int c = (u & 63) * 2;
            float b0 = bias ? bias[n0 + c]     : 0.f;
            float b1 = bias ? bias[n0 + c + 1] : 0.f;
            float v0 = stage[r * STG_S + c]     + b0;
            float v1 = stage[r * STG_S + c + 1] + b1;
            size_t rowb = (size_t)(m0 + r) * Ntot;
            ((__half2*)(outH + rowb + n0 + c))[0] = __floats2half2_rn(v0, v1);
        }
    } else if (MODE == 1) {
        const int b = m0 >> 9, c0 = m0 & 511;
        for (int nl = wid; nl < NT; nl += 8) {
            int n = n0 + nl;
            float bn = bias[n];
            size_t obase = ((size_t)(b * T_ + n)) * C_ + c0;
            #pragma unroll
            for (int cc = 0; cc < 4; cc++) {
                int c = lane + cc * 32;
                outF[obase + c] = res[obase + c] + stage[c * STG_S + nl] + bn;
            }
        }
    } else {
        for (int u = tid; u < 128 * (NT / 4); u += NTHR) {
            int r = u >> 5;
            int c = (u & 31) * 4;
            size_t base = (size_t)(m0 + r) * C_ + n0 + c;
            float4 rv = *(const float4*)(res + base);
            float4 ov;
            ov.x = rv.x + stage[r * STG_S + c]     + bias[n0 + c];
            ov.y = rv.y + stage[r * STG_S + c + 1] + bias[n0 + c + 1];
            ov.z = rv.z + stage[r * STG_S + c + 2] + bias[n0 + c + 2];
            ov.w = rv.w + stage[r * STG_S + c + 3] + bias[n0 + c + 3];
            *(float4*)(outF + base) = ov;
        }
    }
}

// ---------------- launch ----------------
extern "C" void kernel_launch(void* const* d_in, const int* in_sizes, int n_in,
                              void* d_out, int out_size)
{
    const float* x        = (const float*)d_in[0];
    const float* ln1_w    = (const float*)d_in[1];
    const float* ln1_b    = (const float*)d_in[2];
    const float* tok_coef = (const float*)d_in[3];
    const float* tok_kb   = (const float*)d_in[4];
    const float* tok_lw   = (const float*)d_in[5];
    const float* tok_lb   = (const float*)d_in[6];
    const float* ln2_w    = (const float*)d_in[7];
    const float* ln2_b    = (const float*)d_in[8];
    const float* ch_coef  = (const float*)d_in[9];
    const float* ch_kb    = (const float*)d_in[10];
    const float* ch_lw    = (const float*)d_in[11];
    const float* ch_lb    = (const float*)d_in[12];
    float* out = (float*)d_out;

    char* base;
    cudaGetSymbolAddress((void**)&base, g_scratch);
    __half* pF   = (__half*)(base + OFF_F);
    __half* pZ   = (__half*)(base + OFF_Z);
    __half* pCT  = (__half*)(base + OFF_CT);
    __half* pWT  = (__half*)(base + OFF_WT);
    __half* pCP  = (__half*)(base + OFF_CP);
    __half* pCT2 = (__half*)(base + OFF_CT2);
    __half* pLW  = (__half*)(base + OFF_LW16);
    __half* pW2  = (__half*)(base + OFF_W2);
    float*  pB2  = (float*)(base + OFF_B2);
    float2* pSt  = (float2*)(base + OFF_ST);
    float*  pX1  = (float*)(base + OFF_X1);

    cudaFuncSetAttribute(gemm_std<0>, cudaFuncAttributeMaxDynamicSharedMemorySize, SMEMS_SZ);
    cudaFuncSetAttribute(gemm_std<1>, cudaFuncAttributeMaxDynamicSharedMemorySize, SMEMS_SZ);
    cudaFuncSetAttribute(gemm_std<2>, cudaFuncAttributeMaxDynamicSharedMemorySize, SMEMS_SZ);

    // ---- token mixing ----
    ln_stats<<<B_ * T_, 256>>>(x, pSt);
    pack_stage<<<(TD_ * KF + T_ * TD_ + 255) / 256, 256>>>(
        tok_coef, tok_lw, pCT, pWT, TD_, T_ * TD_);
    feat_tok<<<dim3(C_ / 32, T_ / 256, B_), 256>>>(x, pSt, ln1_w, ln1_b, pF);
    // z (M x 256) = F * coef^T + kbias  (fp16 out)
    gemm_std<0><<<dim3(TD_ / NT, MROWS / MT), NTHR, SMEMS_SZ>>>(
        pF, pCT, tok_kb, nullptr, nullptr, pZ, KF, 256);
    // x1 = x + transpose(z * lw^T + lb)
    gemm_std<1><<<dim3(T_ / NT, MROWS / MT), NTHR, SMEMS_SZ>>>(
        pZ, pWT, tok_lb, x, pX1, nullptr, 256, 0);

    // ---- channel mixing (KAN+linear fused via W2 = lw @ C) ----
    pack_stage<<<(1024 * KF + 512 * 1024 + 255) / 256, 256>>>(
        ch_coef, ch_lw, pCP, pLW, 1024, 512 * 1024);
    transpose_ch<<<dim3(KF / 32, 1024 / 32), 256>>>(pCP, pCT2);
    // W2 (512 x 3072) = lw16 (512x1024) @ Ct^T  -> fp16, no bias
    gemm_std<0><<<dim3(KF / NT, 512 / MT), NTHR, SMEMS_SZ>>>(
        pLW, pCT2, nullptr, nullptr, nullptr, pW2, 1024, KF);
    bias2_kernel<<<64, 256>>>(ch_kb, ch_lw, ch_lb, pB2);
    feat_ch<<<B_ * T_, 256>>>(pX1, ln2_w, ln2_b, pF);
    // out = x1 + F @ W2^T + bias2
    gemm_std<2><<<dim3(C_ / NT, MROWS / MT), NTHR, SMEMS_SZ>>>(
        pF, pW2, pB2, pX1, out, nullptr, KF, 512);
}

// round 15
// speedup vs baseline: 1.4339x; 1.0325x over previous
#include <cuda_runtime.h>
#include <cuda_fp16.h>
#include <math.h>
#include <stdint.h>

#define B_  32
#define T_  512
#define C_  512
#define TD_ 256
#define G_  3
#define MROWS 16384
#define KF  3072               // feature K (single stream)

#define MT 128
#define NT 128
#define BK 64
#define NTHR 256
// fp16 gemm smem: per stage A 16K | B 16K = 32K, 3 stages -> 96KB (2 CTA/SM)
#define SOFF_B 16384u
#define SBUF 32768u
#define SMEMS_SZ (3 * 32768)
#define STG_S 133

// ---------------- scratch arena ----------------
#define MB (1024ull * 1024ull)
#define OFF_F     0ull             // features fp16 (16384 x 3072) 96MB (both stages)
#define OFF_Z     (96ull  * MB)    // tok z fp16 (16384 x 256) 8MB
#define OFF_CT    (104ull * MB)    // tok coef (256 x 3072) 1.5MB
#define OFF_WT    (106ull * MB)    // tok lw fp16 (512 x 256) 0.25MB
#define OFF_CP    (108ull * MB)    // ch coef o-major (1024 x 3072) 6MB
#define OFF_CT2   (114ull * MB)    // ch coef k-major (3072 x 1024) 6MB
#define OFF_LW16  (120ull * MB)    // ch lw fp16 (512 x 1024) 1MB
#define OFF_W2    (122ull * MB)    // W2 = lw@C fp16 (512 x 3072) 3MB
#define OFF_B2    (125ull * MB)    // bias2 fp32 (512) 2KB
#define OFF_ST    (126ull * MB)    // LN1 stats float2 per row (128KB)
#define OFF_X1    (128ull * MB)    // x1 fp32 32MB
__device__ __align__(256) char g_scratch[160ull * MB];

// ---------------- PTX helpers ----------------
__device__ __forceinline__ uint32_t smem_u32(const void* p) {
    uint32_t a;
    asm("{ .reg .u64 t; cvta.to.shared.u64 t, %1; cvt.u32.u64 %0, t; }" : "=r"(a) : "l"(p));
    return a;
}
__device__ __forceinline__ void cpasync16(uint32_t dst, const void* src) {
    asm volatile("cp.async.cg.shared.global [%0], [%1], 16;" :: "r"(dst), "l"(src));
}
__device__ __forceinline__ void cp_commit() { asm volatile("cp.async.commit_group;" ::: "memory"); }
__device__ __forceinline__ void cp_wait0()  { asm volatile("cp.async.wait_group 0;" ::: "memory"); }
__device__ __forceinline__ void cp_wait1()  { asm volatile("cp.async.wait_group 1;" ::: "memory"); }
__device__ __forceinline__ void ldsm4(uint32_t addr, uint32_t r[4]) {
    asm volatile("ldmatrix.sync.aligned.m8n8.x4.shared.b16 {%0,%1,%2,%3}, [%4];"
                 : "=r"(r[0]), "=r"(r[1]), "=r"(r[2]), "=r"(r[3]) : "r"(addr));
}
__device__ __forceinline__ void mma_f16(float d[4], const uint32_t a[4], const uint32_t b[2]) {
    asm volatile(
        "mma.sync.aligned.m16n8k16.row.col.f32.f16.f16.f32 "
        "{%0,%1,%2,%3}, {%4,%5,%6,%7}, {%8,%9}, {%0,%1,%2,%3};"
        : "+f"(d[0]), "+f"(d[1]), "+f"(d[2]), "+f"(d[3])
        : "r"(a[0]), "r"(a[1]), "r"(a[2]), "r"(a[3]), "r"(b[0]), "r"(b[1]));
}
// Polynomial sincos, pure FMA pipe, err < 5e-7 for |v| < 30
__device__ __forceinline__ void fast_sincos(float v, float& s, float& c) {
    float k = rintf(v * 0.3183098861837907f);
    float r = fmaf(-k, 3.14159274101257f, v);
    r = fmaf(-k, -8.742277657347586e-8f, r);
    float r2 = r * r;
    float ps = fmaf(r2, -2.5052108385e-8f, 2.7557319224e-6f);
    ps = fmaf(r2, ps, -1.9841269841e-4f);
    ps = fmaf(r2, ps, 8.3333333333e-3f);
    ps = fmaf(r2, ps, -1.6666666667e-1f);
    ps = fmaf(r2, ps, 1.0f);
    float pc = fmaf(r2, -2.7557319224e-7f, 2.4801587302e-5f);
    pc = fmaf(r2, pc, -1.3888888889e-3f);
    pc = fmaf(r2, pc, 4.1666666667e-2f);
    pc = fmaf(r2, pc, -0.5f);
    float sg = (((int)k) & 1) ? -1.0f : 1.0f;
    s = r * ps * sg;
    c = fmaf(r2, pc, 1.0f) * sg;
}

// ---------------- LayerNorm reduce helper (block over one 512-row) ----------
__device__ __forceinline__ void ln_stats_block(float2 v, float& mean, float& rstd) {
    float s  = v.x + v.y;
    float sq = v.x * v.x + v.y * v.y;
    __shared__ float ss[8], sqq[8];
    __shared__ float sm, sr;
    #pragma unroll
    for (int o = 16; o > 0; o >>= 1) {
        s  += __shfl_down_sync(0xffffffffu, s,  o);
        sq += __shfl_down_sync(0xffffffffu, sq, o);
    }
    int lane = threadIdx.x & 31, wid = threadIdx.x >> 5;
    if (lane == 0) { ss[wid] = s; sqq[wid] = sq; }
    __syncthreads();
    if (wid == 0) {
        float a = (lane < 8) ? ss[lane]  : 0.f;
        float q = (lane < 8) ? sqq[lane] : 0.f;
        #pragma unroll
        for (int o = 4; o > 0; o >>= 1) {
            a += __shfl_down_sync(0xffffffffu, a, o);
            q += __shfl_down_sync(0xffffffffu, q, o);
        }
        if (lane == 0) {
            float m = a * (1.0f / 512.f);
            sm = m;
            sr = rsqrtf(q * (1.0f / 512.f) - m * m + 1e-5f);
        }
    }
    __syncthreads();
    mean = sm;
    rstd = sr;
}

// Stats-only LN pass for stage 1
__global__ void ln_stats(const float* __restrict__ x, float2* __restrict__ st)
{
    int row = blockIdx.x;
    float2 v = ((const float2*)(x + (size_t)row * C_))[threadIdx.x];
    float m, r;
    ln_stats_block(v, m, r);
    if (threadIdx.x == 0) st[row] = make_float2(m, r);
}

// ---- packs: coef (2,O,512,3)->fp16 (O x 3072, k=i*6+g*2+trig); lw -> fp16
__global__ void pack_stage(const float* __restrict__ coef, const float* __restrict__ lw,
                           __half* __restrict__ Cd, __half* __restrict__ Wd,
                           int O, int LWTOT)
{
    int idx = blockIdx.x * blockDim.x + threadIdx.x;
    int nc = O * KF;
    if (idx < nc) {
        int o = idx / KF, r = idx % KF;
        int i = r / 6, rr = r % 6, g = rr >> 1, trig = rr & 1;
        Cd[idx] = __float2half_rn(coef[(((size_t)trig * O + o) * 512 + i) * G_ + g]);
    } else {
        int j = idx - nc;
        if (j < LWTOT) Wd[j] = __float2half_rn(lw[j]);
    }
}

// ---- transpose ch coef: Cp (1024 o x 3072 k) -> Ct (3072 k x 1024 o) ----
__global__ __launch_bounds__(256)
void transpose_ch(const __half* __restrict__ Cp, __half* __restrict__ Ct)
{
    __shared__ __half s[32][36];
    int k0 = blockIdx.x * 32, o0 = blockIdx.y * 32;
    int r = threadIdx.x >> 3, c4 = (threadIdx.x & 7) * 4;
    *(uint2*)&s[r][c4] = *(const uint2*)(Cp + (size_t)(o0 + r) * KF + k0 + c4);
    __syncthreads();
    __half tmp[4];
    tmp[0] = s[c4][r]; tmp[1] = s[c4 + 1][r];
    tmp[2] = s[c4 + 2][r]; tmp[3] = s[c4 + 3][r];
    *(uint2*)(Ct + (size_t)(k0 + r) * 1024 + o0 + c4) = *(uint2*)tmp;
}

// ---- bias2[c] = lb[c] + sum_o kb[o]*lw[c,o]  (warp per c) ----
__global__ void bias2_kernel(const float* __restrict__ kb, const float* __restrict__ lw,
                             const float* __restrict__ lb, float* __restrict__ b2)
{
    int c = blockIdx.x * 8 + (threadIdx.x >> 5);
    int lane = threadIdx.x & 31;
    const float* row = lw + (size_t)c * 1024;
    float s = 0.f;
    #pragma unroll 8
    for (int o = lane; o < 1024; o += 32) s += kb[o] * row[o];
    #pragma unroll
    for (int off = 16; off; off >>= 1) s += __shfl_down_sync(0xffffffffu, s, off);
    if (lane == 0) b2[c] = lb[c] + s;
}

// ---- token features: fused LN-apply + expansion; 128-row tile, higher occ ----
__global__ __launch_bounds__(256)
void feat_tok(const float* __restrict__ x, const float2* __restrict__ st,
              const float* __restrict__ lnw, const float* __restrict__ lnb,
              __half* __restrict__ F)
{
    __shared__ float s[128 * 33];
    __shared__ float2 sst[128];
    const int t = threadIdx.x;
    const int c0 = blockIdx.x * 32, i0 = blockIdx.y * 128, b = blockIdx.z;
    #pragma unroll
    for (int it = 0; it < 4; it++) {
        int r = it * 32 + (t >> 3), cc = (t & 7) * 4;
        float4 v = *(const float4*)(x + ((size_t)(b * T_ + i0 + r)) * C_ + c0 + cc);
        s[r * 33 + cc] = v.x; s[r * 33 + cc + 1] = v.y;
        s[r * 33 + cc + 2] = v.z; s[r * 33 + cc + 3] = v.w;
    }
    if (t < 128) sst[t] = st[b * T_ + i0 + t];
    __syncthreads();
    const int w = t >> 5, lane = t & 31;
    #pragma unroll
    for (int rep = 0; rep < 4; rep++) {
        const int cl = w * 4 + rep;
        const float wc = lnw[c0 + cl];
        const float bc = lnb[c0 + cl];
        const size_t n = (size_t)(b * C_ + c0 + cl);
        #pragma unroll
        for (int it2 = 0; it2 < 4; it2++) {
            int il = it2 * 32 + lane;
            float2 mr = sst[il];
            float v = (s[il * 33 + cl] - mr.x) * mr.y * wc + bc;
            float s1, c1;
            fast_sincos(v, s1, c1);
            float c2 = fmaf(2.f * c1, c1, -1.f);
            float s2 = 2.f * s1 * c1;
            float c3 = fmaf(2.f * c1, c2, -c1);
            float s3 = fmaf(2.f * c1, s2, -s1);
            size_t base = n * KF + (size_t)(i0 + il) * 6;
            __half2* p = (__half2*)(F + base);
            p[0] = __floats2half2_rn(c1, s1);
            p[1] = __floats2half2_rn(c2, s2);
            p[2] = __floats2half2_rn(c3, s3);
        }
    }
}

// ---- channel features: fused LN2 + expansion, smem-staged coalesced write ----
__global__ __launch_bounds__(256)
void feat_ch(const float* __restrict__ x1, const float* __restrict__ w,
             const float* __restrict__ b, __half* __restrict__ F)
{
    __shared__ __half fs[KF];
    int row = blockIdx.x;
    float2 v = ((const float2*)(x1 + (size_t)row * C_))[threadIdx.x];
    float m, r;
    ln_stats_block(v, m, r);
    float2 wv = ((const float2*)w)[threadIdx.x];
    float2 bv = ((const float2*)b)[threadIdx.x];
    float ln0 = (v.x - m) * r * wv.x + bv.x;
    float ln1 = (v.y - m) * r * wv.y + bv.y;
    #pragma unroll
    for (int q = 0; q < 2; q++) {
        float vv = q ? ln1 : ln0;
        int c = threadIdx.x * 2 + q;
        float s1, c1;
        fast_sincos(vv, s1, c1);
        float c2 = fmaf(2.f * c1, c1, -1.f);
        float s2 = 2.f * s1 * c1;
        float c3 = fmaf(2.f * c1, c2, -c1);
        float s3 = fmaf(2.f * c1, s2, -s1);
        __half2* p = (__half2*)(fs + (size_t)c * 6);
        p[0] = __floats2half2_rn(c1, s1);
        p[1] = __floats2half2_rn(c2, s2);
        p[2] = __floats2half2_rn(c3, s3);
    }
    __syncthreads();
    // coalesced copy: 3072 halfs = 768 uint2; 256 thr x 3
    const uint2* src = (const uint2*)fs;
    uint2* dst = (uint2*)(F + (size_t)row * KF);
    #pragma unroll
    for (int it = 0; it < 3; it++)
        dst[threadIdx.x + it * 256] = src[threadIdx.x + it * 256];
}

// ---- fp16 TN GEMM, 3-stage cp.async, CTA 128x128, 256 thr, 2 CTAs/SM ----
// MODE 0: fp16 out outH[m*Ntot+n]=D+bias (bias may be null)
// MODE 1: m=(b,c), n=t: outF[(b*T+n)*C+c] = res + D + bias
// MODE 2: outF[m*C+n] = res + D + bias
template<int MODE>
__global__ __launch_bounds__(NTHR, 2)
void gemm_std(const __half* __restrict__ A, const __half* __restrict__ Bm,
              const float* __restrict__ bias, const float* __restrict__ res,
              float* __restrict__ outF, __half* __restrict__ outH,
              int K, int Ntot)
{
    extern __shared__ char smem[];
    const uint32_t sbase = smem_u32(smem);
    const int tid = threadIdx.x, wid = tid >> 5, lane = tid & 31;
    const int m0 = blockIdx.y * MT, n0 = blockIdx.x * NT;
    const int wm = wid >> 1, wn = wid & 1;   // 4x2 warp grid

    float acc[2][8][4];
    #pragma unroll
    for (int i = 0; i < 2; i++)
        #pragma unroll
        for (int j = 0; j < 8; j++)
            #pragma unroll
            for (int q = 0; q < 4; q++) acc[i][j][q] = 0.f;

    const int NC = K >> 6;

    auto load_chunk = [&](int kc, int buf) {
        const uint32_t sb = sbase + (uint32_t)buf * SBUF;
        const size_t kcol = (size_t)kc * BK;
        #pragma unroll
        for (int it = 0; it < 4; it++) {
            int u = tid + it * NTHR;
            int r = u >> 3, cch = u & 7;
            uint32_t off = r * 128 + ((cch ^ (r & 7)) << 4);
            cpasync16(sb + off, (const char*)(A + (size_t)(m0 + r) * K + kcol) + cch * 16);
        }
        #pragma unroll
        for (int it = 0; it < 4; it++) {
            int u = tid + it * NTHR;
            int r = u >> 3, cch = u & 7;
            uint32_t off = r * 128 + ((cch ^ (r & 7)) << 4);
            cpasync16(sb + SOFF_B + off, (const char*)(Bm + (size_t)(n0 + r) * K + kcol) + cch * 16);
        }
    };

    load_chunk(0, 0);
    cp_commit();
    if (NC > 1) load_chunk(1, 1);
    cp_commit();

    const int lr = lane & 7, lq = lane >> 3;

    int cbuf = 0, lbuf = 2;
    for (int kc = 0; kc < NC; kc++) {
        cp_wait1();
        __syncthreads();
        const uint32_t sb = sbase + (uint32_t)cbuf * SBUF;
        #pragma unroll
        for (int k16 = 0; k16 < 4; k16++) {
            uint32_t ah[2][4];
            #pragma unroll
            for (int i = 0; i < 2; i++) {
                int row = wm * 32 + i * 16 + lr + (lq & 1) * 8;
                int ch  = (k16 * 2 + (lq >> 1)) ^ (row & 7);
                ldsm4(sb + row * 128 + (ch << 4), ah[i]);
            }
            #pragma unroll
            for (int jp = 0; jp < 4; jp++) {
                int row = wn * 64 + jp * 16 + lr + (lq >> 1) * 8;
                int ch  = (k16 * 2 + (lq & 1)) ^ (row & 7);
                uint32_t tb[4];
                ldsm4(sb + SOFF_B + row * 128 + (ch << 4), tb);
                #pragma unroll
                for (int i = 0; i < 2; i++) {
                    mma_f16(acc[i][2*jp],   ah[i], tb);
                    mma_f16(acc[i][2*jp+1], ah[i], tb + 2);
                }
            }
        }
        int nk = kc + 2;
        if (nk < NC) load_chunk(nk, lbuf);
        cp_commit();
        cbuf = (cbuf + 1 == 3) ? 0 : cbuf + 1;
        lbuf = (lbuf + 1 == 3) ? 0 : lbuf + 1;
    }
    cp_wait0();
    __syncthreads();

    // stage accumulators to smem
    float* stage = (float*)smem;
    {
        const int g = lane >> 2, t2 = (lane & 3) * 2;
        #pragma unroll
        for (int i = 0; i < 2; i++) {
            int row = wm * 32 + i * 16 + g;
            #pragma unroll
            for (int j = 0; j < 8; j++) {
                int col = wn * 64 + j * 8 + t2;
                stage[row * STG_S + col]           = acc[i][j][0];
                stage[row * STG_S + col + 1]       = acc[i][j][1];
                stage[(row + 8) * STG_S + col]     = acc[i][j][2];
                stage[(row + 8) * STG_S + col + 1] = acc[i][j][3];
            }
        }
    }
    __syncthreads();

    if (MODE == 0) {
        for (int u = tid; u < 128 * (NT / 2); u += NTHR) {
            int r = u >> 6;
            int c = (u & 63) * 2;
            float b0 = bias ? bias[n0 + c]     : 0.f;
            float b1 = bias ? bias[n0 + c + 1] : 0.f;
            float v0 = stage[r * STG_S + c]     + b0;
            float v1 = stage[r * STG_S + c + 1] + b1;
            size_t rowb = (size_t)(m0 + r) * Ntot;
            ((__half2*)(outH + rowb + n0 + c))[0] = __floats2half2_rn(v0, v1);
        }
    } else if (MODE == 1) {
        const int b = m0 >> 9, c0 = m0 & 511;
        for (int nl = wid; nl < NT; nl += 8) {
            int n = n0 + nl;
            float bn = bias[n];
            size_t obase = ((size_t)(b * T_ + n)) * C_ + c0;
            #pragma unroll
            for (int cc = 0; cc < 4; cc++) {
                int c = lane + cc * 32;
                outF[obase + c] = res[obase + c] + stage[c * STG_S + nl] + bn;
            }
        }
    } else {
        for (int u = tid; u < 128 * (NT / 4); u += NTHR) {
            int r = u >> 5;
            int c = (u & 31) * 4;
            size_t base = (size_t)(m0 + r) * C_ + n0 + c;
            float4 rv = *(const float4*)(res + base);
            float4 ov;
            ov.x = rv.x + stage[r * STG_S + c]     + bias[n0 + c];
            ov.y = rv.y + stage[r * STG_S + c + 1] + bias[n0 + c + 1];
            ov.z = rv.z + stage[r * STG_S + c + 2] + bias[n0 + c + 2];
            ov.w = rv.w + stage[r * STG_S + c + 3] + bias[n0 + c + 3];
            *(float4*)(outF + base) = ov;
        }
    }
}

// ---------------- launch ----------------
extern "C" void kernel_launch(void* const* d_in, const int* in_sizes, int n_in,
                              void* d_out, int out_size)
{
    const float* x        = (const float*)d_in[0];
    const float* ln1_w    = (const float*)d_in[1];
    const float* ln1_b    = (const float*)d_in[2];
    const float* tok_coef = (const float*)d_in[3];
    const float* tok_kb   = (const float*)d_in[4];
    const float* tok_lw   = (const float*)d_in[5];
    const float* tok_lb   = (const float*)d_in[6];
    const float* ln2_w    = (const float*)d_in[7];
    const float* ln2_b    = (const float*)d_in[8];
    const float* ch_coef  = (const float*)d_in[9];
    const float* ch_kb    = (const float*)d_in[10];
    const float* ch_lw    = (const float*)d_in[11];
    const float* ch_lb    = (const float*)d_in[12];
    float* out = (float*)d_out;

    char* base;
    cudaGetSymbolAddress((void**)&base, g_scratch);
    __half* pF   = (__half*)(base + OFF_F);
    __half* pZ   = (__half*)(base + OFF_Z);
    __half* pCT  = (__half*)(base + OFF_CT);
    __half* pWT  = (__half*)(base + OFF_WT);
    __half* pCP  = (__half*)(base + OFF_CP);
    __half* pCT2 = (__half*)(base + OFF_CT2);
    __half* pLW  = (__half*)(base + OFF_LW16);
    __half* pW2  = (__half*)(base + OFF_W2);
    float*  pB2  = (float*)(base + OFF_B2);
    float2* pSt  = (float2*)(base + OFF_ST);
    float*  pX1  = (float*)(base + OFF_X1);

    cudaFuncSetAttribute(gemm_std<0>, cudaFuncAttributeMaxDynamicSharedMemorySize, SMEMS_SZ);
    cudaFuncSetAttribute(gemm_std<1>, cudaFuncAttributeMaxDynamicSharedMemorySize, SMEMS_SZ);
    cudaFuncSetAttribute(gemm_std<2>, cudaFuncAttributeMaxDynamicSharedMemorySize, SMEMS_SZ);

    // ---- token mixing ----
    ln_stats<<<B_ * T_, 256>>>(x, pSt);
    pack_stage<<<(TD_ * KF + T_ * TD_ + 255) / 256, 256>>>(
        tok_coef, tok_lw, pCT, pWT, TD_, T_ * TD_);
    feat_tok<<<dim3(C_ / 32, T_ / 128, B_), 256>>>(x, pSt, ln1_w, ln1_b, pF);
    // z (M x 256) = F * coef^T + kbias  (fp16 out)
    gemm_std<0><<<dim3(TD_ / NT, MROWS / MT), NTHR, SMEMS_SZ>>>(
        pF, pCT, tok_kb, nullptr, nullptr, pZ, KF, 256);
    // x1 = x + transpose(z * lw^T + lb)
    gemm_std<1><<<dim3(T_ / NT, MROWS / MT), NTHR, SMEMS_SZ>>>(
        pZ, pWT, tok_lb, x, pX1, nullptr, 256, 0);

    // ---- channel mixing (KAN+linear fused via W2 = lw @ C) ----
    pack_stage<<<(1024 * KF + 512 * 1024 + 255) / 256, 256>>>(
        ch_coef, ch_lw, pCP, pLW, 1024, 512 * 1024);
    transpose_ch<<<dim3(KF / 32, 1024 / 32), 256>>>(pCP, pCT2);
    // W2 (512 x 3072) = lw16 (512x1024) @ Ct^T  -> fp16, no bias
    gemm_std<0><<<dim3(KF / NT, 512 / MT), NTHR, SMEMS_SZ>>>(
        pLW, pCT2, nullptr, nullptr, nullptr, pW2, 1024, KF);
    bias2_kernel<<<64, 256>>>(ch_kb, ch_lw, ch_lb, pB2);
    feat_ch<<<B_ * T_, 256>>>(pX1, ln2_w, ln2_b, pF);
    // out = x1 + F @ W2^T + bias2
    gemm_std<2><<<dim3(C_ / NT, MROWS / MT), NTHR, SMEMS_SZ>>>(
        pF, pW2, pB2, pX1, out, nullptr, KF, 512);
}

// round 16
// speedup vs baseline: 1.4994x; 1.0457x over previous
#include <cuda_runtime.h>
#include <cuda_fp16.h>
#include <math.h>
#include <stdint.h>

#define B_  32
#define T_  512
#define C_  512
#define TD_ 256
#define G_  3
#define MROWS 16384
#define KF  3072               // feature K (single stream)

#define MT 128
#define NT 128
#define BK 64
#define NTHR 256
// fp16 gemm smem: per stage A 16K | B 16K = 32K, 3 stages -> 96KB (2 CTA/SM)
#define SOFF_B 16384u
#define SBUF 32768u
#define SMEMS_SZ (3 * 32768)
#define STG_S 133

// ---------------- scratch arena ----------------
#define MB (1024ull * 1024ull)
#define OFF_F     0ull             // features fp16 (16384 x 3072) 96MB (both stages)
#define OFF_Z     (96ull  * MB)    // tok z fp16 (16384 x 256) 8MB
#define OFF_CT    (104ull * MB)    // tok coef (256 x 3072) 1.5MB
#define OFF_WT    (106ull * MB)    // tok lw fp16 (512 x 256) 0.25MB
#define OFF_CT2   (114ull * MB)    // ch coef k-major (3072 x 1024) 6MB
#define OFF_LW16  (120ull * MB)    // ch lw fp16 (512 x 1024) 1MB
#define OFF_W2    (122ull * MB)    // W2 = lw@C fp16 (512 x 3072) 3MB
#define OFF_B2    (125ull * MB)    // bias2 fp32 (512) 2KB
#define OFF_ST    (126ull * MB)    // LN1 stats float2 per row (128KB)
#define OFF_X1    (128ull * MB)    // x1 fp32 32MB
__device__ __align__(256) char g_scratch[160ull * MB];

// ---------------- PTX helpers ----------------
__device__ __forceinline__ uint32_t smem_u32(const void* p) {
    uint32_t a;
    asm("{ .reg .u64 t; cvta.to.shared.u64 t, %1; cvt.u32.u64 %0, t; }" : "=r"(a) : "l"(p));
    return a;
}
__device__ __forceinline__ void cpasync16(uint32_t dst, const void* src) {
    asm volatile("cp.async.cg.shared.global [%0], [%1], 16;" :: "r"(dst), "l"(src));
}
__device__ __forceinline__ void cp_commit() { asm volatile("cp.async.commit_group;" ::: "memory"); }
__device__ __forceinline__ void cp_wait0()  { asm volatile("cp.async.wait_group 0;" ::: "memory"); }
__device__ __forceinline__ void cp_wait1()  { asm volatile("cp.async.wait_group 1;" ::: "memory"); }
__device__ __forceinline__ void ldsm4(uint32_t addr, uint32_t r[4]) {
    asm volatile("ldmatrix.sync.aligned.m8n8.x4.shared.b16 {%0,%1,%2,%3}, [%4];"
                 : "=r"(r[0]), "=r"(r[1]), "=r"(r[2]), "=r"(r[3]) : "r"(addr));
}
__device__ __forceinline__ void mma_f16(float d[4], const uint32_t a[4], const uint32_t b[2]) {
    asm volatile(
        "mma.sync.aligned.m16n8k16.row.col.f32.f16.f16.f32 "
        "{%0,%1,%2,%3}, {%4,%5,%6,%7}, {%8,%9}, {%0,%1,%2,%3};"
        : "+f"(d[0]), "+f"(d[1]), "+f"(d[2]), "+f"(d[3])
        : "r"(a[0]), "r"(a[1]), "r"(a[2]), "r"(a[3]), "r"(b[0]), "r"(b[1]));
}
// Polynomial sincos, pure FMA pipe, err < 5e-7 for |v| < 30
__device__ __forceinline__ void fast_sincos(float v, float& s, float& c) {
    float k = rintf(v * 0.3183098861837907f);
    float r = fmaf(-k, 3.14159274101257f, v);
    r = fmaf(-k, -8.742277657347586e-8f, r);
    float r2 = r * r;
    float ps = fmaf(r2, -2.5052108385e-8f, 2.7557319224e-6f);
    ps = fmaf(r2, ps, -1.9841269841e-4f);
    ps = fmaf(r2, ps, 8.3333333333e-3f);
    ps = fmaf(r2, ps, -1.6666666667e-1f);
    ps = fmaf(r2, ps, 1.0f);
    float pc = fmaf(r2, -2.7557319224e-7f, 2.4801587302e-5f);
    pc = fmaf(r2, pc, -1.3888888889e-3f);
    pc = fmaf(r2, pc, 4.1666666667e-2f);
    pc = fmaf(r2, pc, -0.5f);
    float sg = (((int)k) & 1) ? -1.0f : 1.0f;
    s = r * ps * sg;
    c = fmaf(r2, pc, 1.0f) * sg;
}

// ---------------- LayerNorm reduce helper (block over one 512-row) ----------
__device__ __forceinline__ void ln_stats_block(float2 v, float& mean, float& rstd) {
    float s  = v.x + v.y;
    float sq = v.x * v.x + v.y * v.y;
    __shared__ float ss[8], sqq[8];
    __shared__ float sm, sr;
    #pragma unroll
    for (int o = 16; o > 0; o >>= 1) {
        s  += __shfl_down_sync(0xffffffffu, s,  o);
        sq += __shfl_down_sync(0xffffffffu, sq, o);
    }
    int lane = threadIdx.x & 31, wid = threadIdx.x >> 5;
    if (lane == 0) { ss[wid] = s; sqq[wid] = sq; }
    __syncthreads();
    if (wid == 0) {
        float a = (lane < 8) ? ss[lane]  : 0.f;
        float q = (lane < 8) ? sqq[lane] : 0.f;
        #pragma unroll
        for (int o = 4; o > 0; o >>= 1) {
            a += __shfl_down_sync(0xffffffffu, a, o);
            q += __shfl_down_sync(0xffffffffu, q, o);
        }
        if (lane == 0) {
            float m = a * (1.0f / 512.f);
            sm = m;
            sr = rsqrtf(q * (1.0f / 512.f) - m * m + 1e-5f);
        }
    }
    __syncthreads();
    mean = sm;
    rstd = sr;
}

// ---------------- merged prep kernel ----------------
// block ranges:
//  [0, 3072)           tok coef pack  (256 x 3072)
//  [3072, 3584)        tok lw pack    (512 x 256)
//  [3584, 5632)        ch lw pack     (512 x 1024)
//  [5632, 5696)        bias2          (512 outputs, 8 warps/block)
//  [5696, 8768)        ch coef gather + transpose tiles (96 k-tiles x 32 o-tiles)
//  [8768, 25152)       LN1 stats rows (16384)
#define PB_TOKC 3072
#define PB_TOKW 3584
#define PB_CHW  5632
#define PB_B2   5696
#define PB_CHT  8768
#define PB_LN   25152
__global__ __launch_bounds__(256)
void prep_kernel(const float* __restrict__ tok_coef, const float* __restrict__ tok_lw,
                 const float* __restrict__ ch_coef,  const float* __restrict__ ch_lw,
                 const float* __restrict__ ch_kb,    const float* __restrict__ ch_lb,
                 const float* __restrict__ x,
                 __half* __restrict__ CT, __half* __restrict__ WT,
                 __half* __restrict__ LW16, __half* __restrict__ CT2,
                 float* __restrict__ B2, float2* __restrict__ ST)
{
    const int blk = blockIdx.x;
    const int t = threadIdx.x;
    if (blk < PB_TOKC) {
        int idx = blk * 256 + t;                    // < 786432
        int o = idx / KF, r = idx % KF;
        int i = r / 6, rr = r % 6, g = rr >> 1, trig = rr & 1;
        CT[idx] = __float2half_rn(tok_coef[(((size_t)trig * TD_ + o) * 512 + i) * G_ + g]);
    } else if (blk < PB_TOKW) {
        int idx = (blk - PB_TOKC) * 256 + t;        // < 131072
        WT[idx] = __float2half_rn(tok_lw[idx]);
    } else if (blk < PB_CHW) {
        int idx = (blk - PB_TOKW) * 256 + t;        // < 524288
        LW16[idx] = __float2half_rn(ch_lw[idx]);
    } else if (blk < PB_B2) {
        int c = (blk - PB_CHW) * 8 + (t >> 5);
        int lane = t & 31;
        const float* row = ch_lw + (size_t)c * 1024;
        float s = 0.f;
        #pragma unroll 8
        for (int o = lane; o < 1024; o += 32) s += ch_kb[o] * row[o];
        #pragma unroll
        for (int off = 16; off; off >>= 1) s += __shfl_down_sync(0xffffffffu, s, off);
        if (lane == 0) B2[c] = ch_lb[c] + s;
    } else if (blk < PB_CHT) {
        // gather ch coef (o-major logical) into smem, write k-major CT2
        __shared__ __half s2[32][36];
        int tile = blk - PB_B2;                     // < 3072
        int k0 = (tile % 96) * 32, o0 = (tile / 96) * 32;
        int r = t >> 3, c4 = (t & 7) * 4;           // r = o-row, c4 = k-col
        #pragma unroll
        for (int j = 0; j < 4; j++) {
            int k = k0 + c4 + j;
            int i = k / 6, rr = k % 6, g = rr >> 1, trig = rr & 1;
            s2[r][c4 + j] = __float2half_rn(
                ch_coef[(((size_t)trig * 1024 + o0 + r) * 512 + i) * G_ + g]);
        }
        __syncthreads();
        __half tmp[4];                              // r now = k-row, c4 = o-cols
        tmp[0] = s2[c4][r]; tmp[1] = s2[c4 + 1][r];
        tmp[2] = s2[c4 + 2][r]; tmp[3] = s2[c4 + 3][r];
        *(uint2*)(CT2 + (size_t)(k0 + r) * 1024 + o0 + c4) = *(uint2*)tmp;
    } else {
        int row = blk - PB_CHT;                     // < 16384
        float2 v = ((const float2*)(x + (size_t)row * C_))[t];
        float m, rs;
        ln_stats_block(v, m, rs);
        if (t == 0) ST[row] = make_float2(m, rs);
    }
}

// ---- token features: fused LN-apply + expansion; 128-row tile ----
__global__ __launch_bounds__(256)
void feat_tok(const float* __restrict__ x, const float2* __restrict__ st,
              const float* __restrict__ lnw, const float* __restrict__ lnb,
              __half* __restrict__ F)
{
    __shared__ float s[128 * 33];
    __shared__ float2 sst[128];
    const int t = threadIdx.x;
    const int c0 = blockIdx.x * 32, i0 = blockIdx.y * 128, b = blockIdx.z;
    #pragma unroll
    for (int it = 0; it < 4; it++) {
        int r = it * 32 + (t >> 3), cc = (t & 7) * 4;
        float4 v = *(const float4*)(x + ((size_t)(b * T_ + i0 + r)) * C_ + c0 + cc);
        s[r * 33 + cc] = v.x; s[r * 33 + cc + 1] = v.y;
        s[r * 33 + cc + 2] = v.z; s[r * 33 + cc + 3] = v.w;
    }
    if (t < 128) sst[t] = st[b * T_ + i0 + t];
    __syncthreads();
    const int w = t >> 5, lane = t & 31;
    #pragma unroll
    for (int rep = 0; rep < 4; rep++) {
        const int cl = w * 4 + rep;
        const float wc = lnw[c0 + cl];
        const float bc = lnb[c0 + cl];
        const size_t n = (size_t)(b * C_ + c0 + cl);
        #pragma unroll
        for (int it2 = 0; it2 < 4; it2++) {
            int il = it2 * 32 + lane;
            float2 mr = sst[il];
            float v = (s[il * 33 + cl] - mr.x) * mr.y * wc + bc;
            float s1, c1;
            fast_sincos(v, s1, c1);
            float c2 = fmaf(2.f * c1, c1, -1.f);
            float s2 = 2.f * s1 * c1;
            float c3 = fmaf(2.f * c1, c2, -c1);
            float s3 = fmaf(2.f * c1, s2, -s1);
            size_t base = n * KF + (size_t)(i0 + il) * 6;
            __half2* p = (__half2*)(F + base);
            p[0] = __floats2half2_rn(c1, s1);
            p[1] = __floats2half2_rn(c2, s2);
            p[2] = __floats2half2_rn(c3, s3);
        }
    }
}

// ---- channel features: fused LN2 + expansion, smem-staged coalesced write ----
__global__ __launch_bounds__(256)
void feat_ch(const float* __restrict__ x1, const float* __restrict__ w,
             const float* __restrict__ b, __half* __restrict__ F)
{
    __shared__ __half fs[KF];
    int row = blockIdx.x;
    float2 v = ((const float2*)(x1 + (size_t)row * C_))[threadIdx.x];
    float m, r;
    ln_stats_block(v, m, r);
    float2 wv = ((const float2*)w)[threadIdx.x];
    float2 bv = ((const float2*)b)[threadIdx.x];
    float ln0 = (v.x - m) * r * wv.x + bv.x;
    float ln1 = (v.y - m) * r * wv.y + bv.y;
    #pragma unroll
    for (int q = 0; q < 2; q++) {
        float vv = q ? ln1 : ln0;
        int c = threadIdx.x * 2 + q;
        float s1, c1;
        fast_sincos(vv, s1, c1);
        float c2 = fmaf(2.f * c1, c1, -1.f);
        float s2 = 2.f * s1 * c1;
        float c3 = fmaf(2.f * c1, c2, -c1);
        float s3 = fmaf(2.f * c1, s2, -s1);
        __half2* p = (__half2*)(fs + (size_t)c * 6);
        p[0] = __floats2half2_rn(c1, s1);
        p[1] = __floats2half2_rn(c2, s2);
        p[2] = __floats2half2_rn(c3, s3);
    }
    __syncthreads();
    const uint2* src = (const uint2*)fs;
    uint2* dst = (uint2*)(F + (size_t)row * KF);
    #pragma unroll
    for (int it = 0; it < 3; it++)
        dst[threadIdx.x + it * 256] = src[threadIdx.x + it * 256];
}

// ---- fp16 TN GEMM, 3-stage cp.async, CTA 128x128, 256 thr, 2 CTAs/SM ----
// MODE 0: fp16 out outH[m*Ntot+n]=D+bias (bias may be null)
// MODE 1: m=(b,c), n=t: outF[(b*T+n)*C+c] = res + D + bias
// MODE 2: outF[m*C+n] = res + D + bias
template<int MODE>
__global__ __launch_bounds__(NTHR, 2)
void gemm_std(const __half* __restrict__ A, const __half* __restrict__ Bm,
              const float* __restrict__ bias, const float* __restrict__ res,
              float* __restrict__ outF, __half* __restrict__ outH,
              int K, int Ntot)
{
    extern __shared__ char smem[];
    const uint32_t sbase = smem_u32(smem);
    const int tid = threadIdx.x, wid = tid >> 5, lane = tid & 31;
    const int m0 = blockIdx.y * MT, n0 = blockIdx.x * NT;
    const int wm = wid >> 1, wn = wid & 1;   // 4x2 warp grid

    float acc[2][8][4];
    #pragma unroll
    for (int i = 0; i < 2; i++)
        #pragma unroll
        for (int j = 0; j < 8; j++)
            #pragma unroll
            for (int q = 0; q < 4; q++) acc[i][j][q] = 0.f;

    const int NC = K >> 6;

    auto load_chunk = [&](int kc, int buf) {
        const uint32_t sb = sbase + (uint32_t)buf * SBUF;
        const size_t kcol = (size_t)kc * BK;
        #pragma unroll
        for (int it = 0; it < 4; it++) {
            int u = tid + it * NTHR;
            int r = u >> 3, cch = u & 7;
            uint32_t off = r * 128 + ((cch ^ (r & 7)) << 4);
            cpasync16(sb + off, (const char*)(A + (size_t)(m0 + r) * K + kcol) + cch * 16);
        }
        #pragma unroll
        for (int it = 0; it < 4; it++) {
            int u = tid + it * NTHR;
            int r = u >> 3, cch = u & 7;
            uint32_t off = r * 128 + ((cch ^ (r & 7)) << 4);
            cpasync16(sb + SOFF_B + off, (const char*)(Bm + (size_t)(n0 + r) * K + kcol) + cch * 16);
        }
    };

    load_chunk(0, 0);
    cp_commit();
    if (NC > 1) load_chunk(1, 1);
    cp_commit();

    const int lr = lane & 7, lq = lane >> 3;

    int cbuf = 0, lbuf = 2;
    for (int kc = 0; kc < NC; kc++) {
        cp_wait1();
        __syncthreads();
        const uint32_t sb = sbase + (uint32_t)cbuf * SBUF;
        #pragma unroll
        for (int k16 = 0; k16 < 4; k16++) {
            uint32_t ah[2][4];
            #pragma unroll
            for (int i = 0; i < 2; i++) {
                int row = wm * 32 + i * 16 + lr + (lq & 1) * 8;
                int ch  = (k16 * 2 + (lq >> 1)) ^ (row & 7);
                ldsm4(sb + row * 128 + (ch << 4), ah[i]);
            }
            #pragma unroll
            for (int jp = 0; jp < 4; jp++) {
                int row = wn * 64 + jp * 16 + lr + (lq >> 1) * 8;
                int ch  = (k16 * 2 + (lq & 1)) ^ (row & 7);
                uint32_t tb[4];
                ldsm4(sb + SOFF_B + row * 128 + (ch << 4), tb);
                #pragma unroll
                for (int i = 0; i < 2; i++) {
                    mma_f16(acc[i][2*jp],   ah[i], tb);
                    mma_f16(acc[i][2*jp+1], ah[i], tb + 2);
                }
            }
        }
        int nk = kc + 2;
        if (nk < NC) load_chunk(nk, lbuf);
        cp_commit();
        cbuf = (cbuf + 1 == 3) ? 0 : cbuf + 1;
        lbuf = (lbuf + 1 == 3) ? 0 : lbuf + 1;
    }
    cp_wait0();
    __syncthreads();

    // stage accumulators to smem
    float* stage = (float*)smem;
    {
        const int g = lane >> 2, t2 = (lane & 3) * 2;
        #pragma unroll
        for (int i = 0; i < 2; i++) {
            int row = wm * 32 + i * 16 + g;
            #pragma unroll
            for (int j = 0; j < 8; j++) {
                int col = wn * 64 + j * 8 + t2;
                stage[row * STG_S + col]           = acc[i][j][0];
                stage[row * STG_S + col + 1]       = acc[i][j][1];
                stage[(row + 8) * STG_S + col]     = acc[i][j][2];
                stage[(row + 8) * STG_S + col + 1] = acc[i][j][3];
            }
        }
    }
    __syncthreads();

    if (MODE == 0) {
        for (int u = tid; u < 128 * (NT / 2); u += NTHR) {
            int r = u >> 6;
            int c = (u & 63) * 2;
            float b0 = bias ? bias[n0 + c]     : 0.f;
            float b1 = bias ? bias[n0 + c + 1] : 0.f;
            float v0 = stage[r * STG_S + c]     + b0;
            float v1 = stage[r * STG_S + c + 1] + b1;
            size_t rowb = (size_t)(m0 + r) * Ntot;
            ((__half2*)(outH + rowb + n0 + c))[0] = __floats2half2_rn(v0, v1);
        }
    } else if (MODE == 1) {
        const int b = m0 >> 9, c0 = m0 & 511;
        for (int nl = wid; nl < NT; nl += 8) {
            int n = n0 + nl;
            float bn = bias[n];
            size_t obase = ((size_t)(b * T_ + n)) * C_ + c0;
            #pragma unroll
            for (int cc = 0; cc < 4; cc++) {
                int c = lane + cc * 32;
                outF[obase + c] = res[obase + c] + stage[c * STG_S + nl] + bn;
            }
        }
    } else {
        for (int u = tid; u < 128 * (NT / 4); u += NTHR) {
            int r = u >> 5;
            int c = (u & 31) * 4;
            size_t base = (size_t)(m0 + r) * C_ + n0 + c;
            float4 rv = *(const float4*)(res + base);
            float4 ov;
            ov.x = rv.x + stage[r * STG_S + c]     + bias[n0 + c];
            ov.y = rv.y + stage[r * STG_S + c + 1] + bias[n0 + c + 1];
            ov.z = rv.z + stage[r * STG_S + c + 2] + bias[n0 + c + 2];
            ov.w = rv.w + stage[r * STG_S + c + 3] + bias[n0 + c + 3];
            *(float4*)(outF + base) = ov;
        }
    }
}

// ---------------- launch ----------------
extern "C" void kernel_launch(void* const* d_in, const int* in_sizes, int n_in,
                              void* d_out, int out_size)
{
    const float* x        = (const float*)d_in[0];
    const float* ln1_w    = (const float*)d_in[1];
    const float* ln1_b    = (const float*)d_in[2];
    const float* tok_coef = (const float*)d_in[3];
    const float* tok_kb   = (const float*)d_in[4];
    const float* tok_lw   = (const float*)d_in[5];
    const float* tok_lb   = (const float*)d_in[6];
    const float* ln2_w    = (const float*)d_in[7];
    const float* ln2_b    = (const float*)d_in[8];
    const float* ch_coef  = (const float*)d_in[9];
    const float* ch_kb    = (const float*)d_in[10];
    const float* ch_lw    = (const float*)d_in[11];
    const float* ch_lb    = (const float*)d_in[12];
    float* out = (float*)d_out;

    char* base;
    cudaGetSymbolAddress((void**)&base, g_scratch);
    __half* pF   = (__half*)(base + OFF_F);
    __half* pZ   = (__half*)(base + OFF_Z);
    __half* pCT  = (__half*)(base + OFF_CT);
    __half* pWT  = (__half*)(base + OFF_WT);
    __half* pCT2 = (__half*)(base + OFF_CT2);
    __half* pLW  = (__half*)(base + OFF_LW16);
    __half* pW2  = (__half*)(base + OFF_W2);
    float*  pB2  = (float*)(base + OFF_B2);
    float2* pSt  = (float2*)(base + OFF_ST);
    float*  pX1  = (float*)(base + OFF_X1);

    cudaFuncSetAttribute(gemm_std<0>, cudaFuncAttributeMaxDynamicSharedMemorySize, SMEMS_SZ);
    cudaFuncSetAttribute(gemm_std<1>, cudaFuncAttributeMaxDynamicSharedMemorySize, SMEMS_SZ);
    cudaFuncSetAttribute(gemm_std<2>, cudaFuncAttributeMaxDynamicSharedMemorySize, SMEMS_SZ);

    // ---- merged prep (all packs + transpose + bias2 + LN1 stats) ----
    prep_kernel<<<PB_LN, 256>>>(tok_coef, tok_lw, ch_coef, ch_lw, ch_kb, ch_lb, x,
                                pCT, pWT, pLW, pCT2, pB2, pSt);

    // ---- token mixing ----
    feat_tok<<<dim3(C_ / 32, T_ / 128, B_), 256>>>(x, pSt, ln1_w, ln1_b, pF);
    // z (M x 256) = F * coef^T + kbias  (fp16 out)
    gemm_std<0><<<dim3(TD_ / NT, MROWS / MT), NTHR, SMEMS_SZ>>>(
        pF, pCT, tok_kb, nullptr, nullptr, pZ, KF, 256);
    // x1 = x + transpose(z * lw^T + lb)
    gemm_std<1><<<dim3(T_ / NT, MROWS / MT), NTHR, SMEMS_SZ>>>(
        pZ, pWT, tok_lb, x, pX1, nullptr, 256, 0);

    // ---- channel mixing (KAN+linear fused via W2 = lw @ C) ----
    // W2 (512 x 3072) = lw16 (512x1024) @ Ct2^T  -> fp16, no bias
    gemm_std<0><<<dim3(KF / NT, 512 / MT), NTHR, SMEMS_SZ>>>(
        pLW, pCT2, nullptr, nullptr, nullptr, pW2, 1024, KF);
    feat_ch<<<B_ * T_, 256>>>(pX1, ln2_w, ln2_b, pF);
    // out = x1 + F @ W2^T + bias2
    gemm_std<2><<<dim3(C_ / NT, MROWS / MT), NTHR, SMEMS_SZ>>>(
        pF, pW2, pB2, pX1, out, nullptr, KF, 512);
}

// round 17
// speedup vs baseline: 1.5429x; 1.0290x over previous
#include <cuda_runtime.h>
#include <cuda_fp16.h>
#include <math.h>
#include <stdint.h>

#define B_  32
#define T_  512
#define C_  512
#define TD_ 256
#define G_  3
#define MROWS 16384
#define KF  3072               // feature K (single stream)

#define MT 128
#define NT 128
#define BK 64
#define NTHR 256
// fp16 gemm smem: per stage A 16K | B 16K = 32K, 3 stages -> 96KB (2 CTA/SM)
#define SOFF_B 16384u
#define SBUF 32768u
#define SMEMS_SZ (3 * 32768)
#define STG_S 133

// ---------------- scratch arena ----------------
#define MB (1024ull * 1024ull)
#define OFF_F     0ull             // features fp16 (16384 x 3072) 96MB (both stages)
#define OFF_Z     (96ull  * MB)    // tok z fp16 (16384 x 256) 8MB
#define OFF_CT    (104ull * MB)    // tok coef (256 x 3072) 1.5MB
#define OFF_WT    (106ull * MB)    // tok lw fp16 (512 x 256) 0.25MB
#define OFF_CT2   (114ull * MB)    // ch coef k-major (3072 x 1024) 6MB
#define OFF_LW16  (120ull * MB)    // ch lw fp16 (512 x 1024) 1MB
#define OFF_W2    (122ull * MB)    // W2 = lw@C fp16 (512 x 3072) 3MB
#define OFF_B2    (125ull * MB)    // bias2 fp32 (512) 2KB
#define OFF_ST    (126ull * MB)    // LN1 stats float2 per row (128KB)
#define OFF_X1    (128ull * MB)    // x1 fp32 32MB
__device__ __align__(256) char g_scratch[160ull * MB];

// ---------------- PTX helpers ----------------
__device__ __forceinline__ uint32_t smem_u32(const void* p) {
    uint32_t a;
    asm("{ .reg .u64 t; cvta.to.shared.u64 t, %1; cvt.u32.u64 %0, t; }" : "=r"(a) : "l"(p));
    return a;
}
__device__ __forceinline__ void cpasync16(uint32_t dst, const void* src) {
    asm volatile("cp.async.cg.shared.global [%0], [%1], 16;" :: "r"(dst), "l"(src));
}
__device__ __forceinline__ void cp_commit() { asm volatile("cp.async.commit_group;" ::: "memory"); }
__device__ __forceinline__ void cp_wait0()  { asm volatile("cp.async.wait_group 0;" ::: "memory"); }
__device__ __forceinline__ void cp_wait1()  { asm volatile("cp.async.wait_group 1;" ::: "memory"); }
__device__ __forceinline__ void ldsm4(uint32_t addr, uint32_t r[4]) {
    asm volatile("ldmatrix.sync.aligned.m8n8.x4.shared.b16 {%0,%1,%2,%3}, [%4];"
                 : "=r"(r[0]), "=r"(r[1]), "=r"(r[2]), "=r"(r[3]) : "r"(addr));
}
__device__ __forceinline__ void mma_f16(float d[4], const uint32_t a[4], const uint32_t b[2]) {
    asm volatile(
        "mma.sync.aligned.m16n8k16.row.col.f32.f16.f16.f32 "
        "{%0,%1,%2,%3}, {%4,%5,%6,%7}, {%8,%9}, {%0,%1,%2,%3};"
        : "+f"(d[0]), "+f"(d[1]), "+f"(d[2]), "+f"(d[3])
        : "r"(a[0]), "r"(a[1]), "r"(a[2]), "r"(a[3]), "r"(b[0]), "r"(b[1]));
}
// Polynomial sincos, pure FMA pipe, err < 5e-7 for |v| < 30
__device__ __forceinline__ void fast_sincos(float v, float& s, float& c) {
    float k = rintf(v * 0.3183098861837907f);
    float r = fmaf(-k, 3.14159274101257f, v);
    r = fmaf(-k, -8.742277657347586e-8f, r);
    float r2 = r * r;
    float ps = fmaf(r2, -2.5052108385e-8f, 2.7557319224e-6f);
    ps = fmaf(r2, ps, -1.9841269841e-4f);
    ps = fmaf(r2, ps, 8.3333333333e-3f);
    ps = fmaf(r2, ps, -1.6666666667e-1f);
    ps = fmaf(r2, ps, 1.0f);
    float pc = fmaf(r2, -2.7557319224e-7f, 2.4801587302e-5f);
    pc = fmaf(r2, pc, -1.3888888889e-3f);
    pc = fmaf(r2, pc, 4.1666666667e-2f);
    pc = fmaf(r2, pc, -0.5f);
    float sg = (((int)k) & 1) ? -1.0f : 1.0f;
    s = r * ps * sg;
    c = fmaf(r2, pc, 1.0f) * sg;
}

// ---------------- LayerNorm reduce helper (block over one 512-row) ----------
__device__ __forceinline__ void ln_stats_block(float2 v, float& mean, float& rstd) {
    float s  = v.x + v.y;
    float sq = v.x * v.x + v.y * v.y;
    __shared__ float ss[8], sqq[8];
    __shared__ float sm, sr;
    #pragma unroll
    for (int o = 16; o > 0; o >>= 1) {
        s  += __shfl_down_sync(0xffffffffu, s,  o);
        sq += __shfl_down_sync(0xffffffffu, sq, o);
    }
    int lane = threadIdx.x & 31, wid = threadIdx.x >> 5;
    if (lane == 0) { ss[wid] = s; sqq[wid] = sq; }
    __syncthreads();
    if (wid == 0) {
        float a = (lane < 8) ? ss[lane]  : 0.f;
        float q = (lane < 8) ? sqq[lane] : 0.f;
        #pragma unroll
        for (int o = 4; o > 0; o >>= 1) {
            a += __shfl_down_sync(0xffffffffu, a, o);
            q += __shfl_down_sync(0xffffffffu, q, o);
        }
        if (lane == 0) {
            float m = a * (1.0f / 512.f);
            sm = m;
            sr = rsqrtf(q * (1.0f / 512.f) - m * m + 1e-5f);
        }
    }
    __syncthreads();
    mean = sm;
    rstd = sr;
}

// ---------------- merged prep kernel ----------------
#define PB_TOKC 3072
#define PB_TOKW 3584
#define PB_CHW  5632
#define PB_B2   5696
#define PB_CHT  8768
#define PB_LN   25152
__global__ __launch_bounds__(256)
void prep_kernel(const float* __restrict__ tok_coef, const float* __restrict__ tok_lw,
                 const float* __restrict__ ch_coef,  const float* __restrict__ ch_lw,
                 const float* __restrict__ ch_kb,    const float* __restrict__ ch_lb,
                 const float* __restrict__ x,
                 __half* __restrict__ CT, __half* __restrict__ WT,
                 __half* __restrict__ LW16, __half* __restrict__ CT2,
                 float* __restrict__ B2, float2* __restrict__ ST)
{
    const int blk = blockIdx.x;
    const int t = threadIdx.x;
    if (blk < PB_TOKC) {
        int idx = blk * 256 + t;
        int o = idx / KF, r = idx % KF;
        int i = r / 6, rr = r % 6, g = rr >> 1, trig = rr & 1;
        CT[idx] = __float2half_rn(tok_coef[(((size_t)trig * TD_ + o) * 512 + i) * G_ + g]);
    } else if (blk < PB_TOKW) {
        int idx = (blk - PB_TOKC) * 256 + t;
        WT[idx] = __float2half_rn(tok_lw[idx]);
    } else if (blk < PB_CHW) {
        int idx = (blk - PB_TOKW) * 256 + t;
        LW16[idx] = __float2half_rn(ch_lw[idx]);
    } else if (blk < PB_B2) {
        int c = (blk - PB_CHW) * 8 + (t >> 5);
        int lane = t & 31;
        const float* row = ch_lw + (size_t)c * 1024;
        float s = 0.f;
        #pragma unroll 8
        for (int o = lane; o < 1024; o += 32) s += ch_kb[o] * row[o];
        #pragma unroll
        for (int off = 16; off; off >>= 1) s += __shfl_down_sync(0xffffffffu, s, off);
        if (lane == 0) B2[c] = ch_lb[c] + s;
    } else if (blk < PB_CHT) {
        __shared__ __half s2[32][36];
        int tile = blk - PB_B2;
        int k0 = (tile % 96) * 32, o0 = (tile / 96) * 32;
        int r = t >> 3, c4 = (t & 7) * 4;
        #pragma unroll
        for (int j = 0; j < 4; j++) {
            int k = k0 + c4 + j;
            int i = k / 6, rr = k % 6, g = rr >> 1, trig = rr & 1;
            s2[r][c4 + j] = __float2half_rn(
                ch_coef[(((size_t)trig * 1024 + o0 + r) * 512 + i) * G_ + g]);
        }
        __syncthreads();
        __half tmp[4];
        tmp[0] = s2[c4][r]; tmp[1] = s2[c4 + 1][r];
        tmp[2] = s2[c4 + 2][r]; tmp[3] = s2[c4 + 3][r];
        *(uint2*)(CT2 + (size_t)(k0 + r) * 1024 + o0 + c4) = *(uint2*)tmp;
    } else {
        int row = blk - PB_CHT;
        float2 v = ((const float2*)(x + (size_t)row * C_))[t];
        float m, rs;
        ln_stats_block(v, m, rs);
        if (t == 0) ST[row] = make_float2(m, rs);
    }
}

// ---- token features: fused LN-apply + expansion; 128-row tile ----
__global__ __launch_bounds__(256)
void feat_tok(const float* __restrict__ x, const float2* __restrict__ st,
              const float* __restrict__ lnw, const float* __restrict__ lnb,
              __half* __restrict__ F)
{
    __shared__ float s[128 * 33];
    __shared__ float2 sst[128];
    const int t = threadIdx.x;
    const int c0 = blockIdx.x * 32, i0 = blockIdx.y * 128, b = blockIdx.z;
    #pragma unroll
    for (int it = 0; it < 4; it++) {
        int r = it * 32 + (t >> 3), cc = (t & 7) * 4;
        float4 v = *(const float4*)(x + ((size_t)(b * T_ + i0 + r)) * C_ + c0 + cc);
        s[r * 33 + cc] = v.x; s[r * 33 + cc + 1] = v.y;
        s[r * 33 + cc + 2] = v.z; s[r * 33 + cc + 3] = v.w;
    }
    if (t < 128) sst[t] = st[b * T_ + i0 + t];
    __syncthreads();
    const int w = t >> 5, lane = t & 31;
    #pragma unroll
    for (int rep = 0; rep < 4; rep++) {
        const int cl = w * 4 + rep;
        const float wc = lnw[c0 + cl];
        const float bc = lnb[c0 + cl];
        const size_t n = (size_t)(b * C_ + c0 + cl);
        #pragma unroll
        for (int it2 = 0; it2 < 4; it2++) {
            int il = it2 * 32 + lane;
            float2 mr = sst[il];
            float v = (s[il * 33 + cl] - mr.x) * mr.y * wc + bc;
            float s1, c1;
            fast_sincos(v, s1, c1);
            float c2 = fmaf(2.f * c1, c1, -1.f);
            float s2 = 2.f * s1 * c1;
            float c3 = fmaf(2.f * c1, c2, -c1);
            float s3 = fmaf(2.f * c1, s2, -s1);
            size_t base = n * KF + (size_t)(i0 + il) * 6;
            __half2* p = (__half2*)(F + base);
            p[0] = __floats2half2_rn(c1, s1);
            p[1] = __floats2half2_rn(c2, s2);
            p[2] = __floats2half2_rn(c3, s3);
        }
    }
}

// ---- channel features: fused LN2 + expansion, smem-staged coalesced write ----
__global__ __launch_bounds__(256)
void feat_ch(const float* __restrict__ x1, const float* __restrict__ w,
             const float* __restrict__ b, __half* __restrict__ F)
{
    __shared__ __half fs[KF];
    int row = blockIdx.x;
    float2 v = ((const float2*)(x1 + (size_t)row * C_))[threadIdx.x];
    float m, r;
    ln_stats_block(v, m, r);
    float2 wv = ((const float2*)w)[threadIdx.x];
    float2 bv = ((const float2*)b)[threadIdx.x];
    float ln0 = (v.x - m) * r * wv.x + bv.x;
    float ln1 = (v.y - m) * r * wv.y + bv.y;
    #pragma unroll
    for (int q = 0; q < 2; q++) {
        float vv = q ? ln1 : ln0;
        int c = threadIdx.x * 2 + q;
        float s1, c1;
        fast_sincos(vv, s1, c1);
        float c2 = fmaf(2.f * c1, c1, -1.f);
        float s2 = 2.f * s1 * c1;
        float c3 = fmaf(2.f * c1, c2, -c1);
        float s3 = fmaf(2.f * c1, s2, -s1);
        __half2* p = (__half2*)(fs + (size_t)c * 6);
        p[0] = __floats2half2_rn(c1, s1);
        p[1] = __floats2half2_rn(c2, s2);
        p[2] = __floats2half2_rn(c3, s3);
    }
    __syncthreads();
    const uint2* src = (const uint2*)fs;
    uint2* dst = (uint2*)(F + (size_t)row * KF);
    #pragma unroll
    for (int it = 0; it < 3; it++)
        dst[threadIdx.x + it * 256] = src[threadIdx.x + it * 256];
}

// ---- fp16 TN GEMM, 3-stage cp.async, CTA 128x128, 256 thr, 2 CTAs/SM ----
// MODE 0: fp16 out outH[m*Ntot+n]=D+bias (bias may be null)
// MODE 1: m=(b,c), n=t: outF[(b*T+n)*C+c] = res + D + bias
// MODE 2: outF[m*C+n] = res + D + bias
template<int MODE>
__global__ __launch_bounds__(NTHR, 2)
void gemm_std(const __half* __restrict__ A, const __half* __restrict__ Bm,
              const float* __restrict__ bias, const float* __restrict__ res,
              float* __restrict__ outF, __half* __restrict__ outH,
              int K, int Ntot)
{
    extern __shared__ char smem[];
    const uint32_t sbase = smem_u32(smem);
    const int tid = threadIdx.x, wid = tid >> 5, lane = tid & 31;
    const int m0 = blockIdx.y * MT, n0 = blockIdx.x * NT;
    const int wm = wid >> 1, wn = wid & 1;   // 4x2 warp grid

    float acc[2][8][4];
    #pragma unroll
    for (int i = 0; i < 2; i++)
        #pragma unroll
        for (int j = 0; j < 8; j++)
            #pragma unroll
            for (int q = 0; q < 4; q++) acc[i][j][q] = 0.f;

    const int NC = K >> 6;

    auto load_chunk = [&](int kc, int buf) {
        const uint32_t sb = sbase + (uint32_t)buf * SBUF;
        const size_t kcol = (size_t)kc * BK;
        #pragma unroll
        for (int it = 0; it < 4; it++) {
            int u = tid + it * NTHR;
            int r = u >> 3, cch = u & 7;
            uint32_t off = r * 128 + ((cch ^ (r & 7)) << 4);
            cpasync16(sb + off, (const char*)(A + (size_t)(m0 + r) * K + kcol) + cch * 16);
        }
        #pragma unroll
        for (int it = 0; it < 4; it++) {
            int u = tid + it * NTHR;
            int r = u >> 3, cch = u & 7;
            uint32_t off = r * 128 + ((cch ^ (r & 7)) << 4);
            cpasync16(sb + SOFF_B + off, (const char*)(Bm + (size_t)(n0 + r) * K + kcol) + cch * 16);
        }
    };

    load_chunk(0, 0);
    cp_commit();
    if (NC > 1) load_chunk(1, 1);
    cp_commit();

    const int lr = lane & 7, lq = lane >> 3;

    int cbuf = 0, lbuf = 2;
    for (int kc = 0; kc < NC; kc++) {
        cp_wait1();
        __syncthreads();
        const uint32_t sb = sbase + (uint32_t)cbuf * SBUF;
        #pragma unroll
        for (int k16 = 0; k16 < 4; k16++) {
            uint32_t ah[2][4];
            #pragma unroll
            for (int i = 0; i < 2; i++) {
                int row = wm * 32 + i * 16 + lr + (lq & 1) * 8;
                int ch  = (k16 * 2 + (lq >> 1)) ^ (row & 7);
                ldsm4(sb + row * 128 + (ch << 4), ah[i]);
            }
            #pragma unroll
            for (int jp = 0; jp < 4; jp++) {
                int row = wn * 64 + jp * 16 + lr + (lq >> 1) * 8;
                int ch  = (k16 * 2 + (lq & 1)) ^ (row & 7);
                uint32_t tb[4];
                ldsm4(sb + SOFF_B + row * 128 + (ch << 4), tb);
                #pragma unroll
                for (int i = 0; i < 2; i++) {
                    mma_f16(acc[i][2*jp],   ah[i], tb);
                    mma_f16(acc[i][2*jp+1], ah[i], tb + 2);
                }
            }
        }
        int nk = kc + 2;
        if (nk < NC) load_chunk(nk, lbuf);
        cp_commit();
        cbuf = (cbuf + 1 == 3) ? 0 : cbuf + 1;
        lbuf = (lbuf + 1 == 3) ? 0 : lbuf + 1;
    }
    cp_wait0();
    __syncthreads();

    // stage accumulators to smem
    float* stage = (float*)smem;
    {
        const int g = lane >> 2, t2 = (lane & 3) * 2;
        #pragma unroll
        for (int i = 0; i < 2; i++) {
            int row = wm * 32 + i * 16 + g;
            #pragma unroll
            for (int j = 0; j < 8; j++) {
                int col = wn * 64 + j * 8 + t2;
                stage[row * STG_S + col]           = acc[i][j][0];
                stage[row * STG_S + col + 1]       = acc[i][j][1];
                stage[(row + 8) * STG_S + col]     = acc[i][j][2];
                stage[(row + 8) * STG_S + col + 1] = acc[i][j][3];
            }
        }
    }
    __syncthreads();

    if (MODE == 0) {
        for (int u = tid; u < 128 * (NT / 2); u += NTHR) {
            int r = u >> 6;
            int c = (u & 63) * 2;
            float b0 = bias ? bias[n0 + c]     : 0.f;
            float b1 = bias ? bias[n0 + c + 1] : 0.f;
            float v0 = stage[r * STG_S + c]     + b0;
            float v1 = stage[r * STG_S + c + 1] + b1;
            size_t rowb = (size_t)(m0 + r) * Ntot;
            ((__half2*)(outH + rowb + n0 + c))[0] = __floats2half2_rn(v0, v1);
        }
    } else if (MODE == 1) {
        const int b = m0 >> 9, c0 = m0 & 511;
        for (int nl = wid; nl < NT; nl += 8) {
            int n = n0 + nl;
            float bn = bias[n];
            size_t obase = ((size_t)(b * T_ + n)) * C_ + c0;
            #pragma unroll
            for (int cc = 0; cc < 4; cc++) {
                int c = lane + cc * 32;
                outF[obase + c] = res[obase + c] + stage[c * STG_S + nl] + bn;
            }
        }
    } else {
        for (int u = tid; u < 128 * (NT / 4); u += NTHR) {
            int r = u >> 5;
            int c = (u & 31) * 4;
            size_t base = (size_t)(m0 + r) * C_ + n0 + c;
            float4 rv = *(const float4*)(res + base);
            float4 ov;
            ov.x = rv.x + stage[r * STG_S + c]     + bias[n0 + c];
            ov.y = rv.y + stage[r * STG_S + c + 1] + bias[n0 + c + 1];
            ov.z = rv.z + stage[r * STG_S + c + 2] + bias[n0 + c + 2];
            ov.w = rv.w + stage[r * STG_S + c + 3] + bias[n0 + c + 3];
            *(float4*)(outF + base) = ov;
        }
    }
}

// ---------------- launch ----------------
extern "C" void kernel_launch(void* const* d_in, const int* in_sizes, int n_in,
                              void* d_out, int out_size)
{
    const float* x        = (const float*)d_in[0];
    const float* ln1_w    = (const float*)d_in[1];
    const float* ln1_b    = (const float*)d_in[2];
    const float* tok_coef = (const float*)d_in[3];
    const float* tok_kb   = (const float*)d_in[4];
    const float* tok_lw   = (const float*)d_in[5];
    const float* tok_lb   = (const float*)d_in[6];
    const float* ln2_w    = (const float*)d_in[7];
    const float* ln2_b    = (const float*)d_in[8];
    const float* ch_coef  = (const float*)d_in[9];
    const float* ch_kb    = (const float*)d_in[10];
    const float* ch_lw    = (const float*)d_in[11];
    const float* ch_lb    = (const float*)d_in[12];
    float* out = (float*)d_out;

    char* base;
    cudaGetSymbolAddress((void**)&base, g_scratch);
    __half* pF   = (__half*)(base + OFF_F);
    __half* pZ   = (__half*)(base + OFF_Z);
    __half* pCT  = (__half*)(base + OFF_CT);
    __half* pWT  = (__half*)(base + OFF_WT);
    __half* pCT2 = (__half*)(base + OFF_CT2);
    __half* pLW  = (__half*)(base + OFF_LW16);
    __half* pW2  = (__half*)(base + OFF_W2);
    float*  pB2  = (float*)(base + OFF_B2);
    float2* pSt  = (float2*)(base + OFF_ST);
    float*  pX1  = (float*)(base + OFF_X1);

    // one-time resources (host-side only; no device allocation)
    static cudaStream_t s2 = nullptr;
    static cudaEvent_t ev1 = nullptr, ev2 = nullptr;
    if (s2 == nullptr) {
        cudaStreamCreateWithFlags(&s2, cudaStreamNonBlocking);
        cudaEventCreateWithFlags(&ev1, cudaEventDisableTiming);
        cudaEventCreateWithFlags(&ev2, cudaEventDisableTiming);
        cudaFuncSetAttribute(gemm_std<0>, cudaFuncAttributeMaxDynamicSharedMemorySize, SMEMS_SZ);
        cudaFuncSetAttribute(gemm_std<1>, cudaFuncAttributeMaxDynamicSharedMemorySize, SMEMS_SZ);
        cudaFuncSetAttribute(gemm_std<2>, cudaFuncAttributeMaxDynamicSharedMemorySize, SMEMS_SZ);
    }

    // ---- merged prep (all packs + transpose + bias2 + LN1 stats) ----
    prep_kernel<<<PB_LN, 256>>>(tok_coef, tok_lw, ch_coef, ch_lw, ch_kb, ch_lb, x,
                                pCT, pWT, pLW, pCT2, pB2, pSt);
    cudaEventRecord(ev1, 0);

    // ---- channel weight pre-contraction on side stream (overlaps token path) ----
    cudaStreamWaitEvent(s2, ev1, 0);
    gemm_std<0><<<dim3(KF / NT, 512 / MT), NTHR, SMEMS_SZ, s2>>>(
        pLW, pCT2, nullptr, nullptr, nullptr, pW2, 1024, KF);
    cudaEventRecord(ev2, s2);

    // ---- token mixing (default stream) ----
    feat_tok<<<dim3(C_ / 32, T_ / 128, B_), 256>>>(x, pSt, ln1_w, ln1_b, pF);
    gemm_std<0><<<dim3(TD_ / NT, MROWS / MT), NTHR, SMEMS_SZ>>>(
        pF, pCT, tok_kb, nullptr, nullptr, pZ, KF, 256);
    gemm_std<1><<<dim3(T_ / NT, MROWS / MT), NTHR, SMEMS_SZ>>>(
        pZ, pWT, tok_lb, x, pX1, nullptr, 256, 0);

    // ---- channel mixing ----
    feat_ch<<<B_ * T_, 256>>>(pX1, ln2_w, ln2_b, pF);
    cudaStreamWaitEvent(0, ev2, 0);
    // out = x1 + F @ W2^T + bias2
    gemm_std<2><<<dim3(C_ / NT, MROWS / MT), NTHR, SMEMS_SZ>>>(
        pF, pW2, pB2, pX1, out, nullptr, KF, 512);
}